// round 5
// baseline (speedup 1.0000x reference)
#include <cuda_runtime.h>

#define NSMP   32768
#define TSTEPS 512
#define HID    64
#define NTHR   448
#define NCTA   147   // 147*448 = 65856 >= 2*32768

typedef unsigned long long ull;

// ---- packed f32x2 helpers (FFMA2 is PTX-only; ptxas never emits it from C++) ----
__device__ __forceinline__ ull fma2(ull a, ull b, ull c) {
    ull d;
    asm("fma.rn.f32x2 %0, %1, %2, %3;" : "=l"(d) : "l"(a), "l"(b), "l"(c));
    return d;
}
__device__ __forceinline__ ull add2(ull a, ull b) {
    ull d;
    asm("add.rn.f32x2 %0, %1, %2;" : "=l"(d) : "l"(a), "l"(b));
    return d;
}
__device__ __forceinline__ ull pack2(float x) {
    ull d;
    asm("mov.b64 %0, {%1, %1};" : "=l"(d) : "f"(x));
    return d;
}
__device__ __forceinline__ float2 unpack2(ull v) {
    float lo, hi;
    asm("mov.b64 {%0, %1}, %2;" : "=f"(lo), "=f"(hi) : "l"(v));
    return make_float2(lo, hi);
}

__device__ __forceinline__ float lipswish(float x) {
    float s = __fdividef(1.0f, 1.0f + __expf(-x));
    return 0.909f * x * s;
}
__device__ __forceinline__ float softplus_acc(float x) {
    return fmaxf(x, 0.0f) + log1pf(__expf(-fabsf(x)));
}

// Hidden dense layer 64->64, pair-split: this thread produces output columns
// [ob, ob+32) from input vector h, whose own half lives in own[32] and whose
// other half is fetched from the pair partner via shfl.bfly(1).
// Row order: own rows first, then partner rows (fp32 reassociation only).
__device__ __forceinline__ void dense64_pair(const float* __restrict__ W,
                                             const float* __restrict__ B,
                                             float (&own)[32], int ob) {
    ull acc[16];
    const ulonglong2* bb = reinterpret_cast<const ulonglong2*>(B + ob);
#pragma unroll
    for (int j = 0; j < 8; j++) {
        ulonglong2 b = bb[j];
        acc[2 * j] = b.x;
        acc[2 * j + 1] = b.y;
    }
    // phase 1: rows ob..ob+31 (inputs held locally)
#pragma unroll
    for (int i = 0; i < 32; i++) {
        ull aa = pack2(own[i]);
        const ulonglong2* w =
            reinterpret_cast<const ulonglong2*>(W + (ob + i) * HID + ob);
#pragma unroll
        for (int j = 0; j < 8; j++) {
            ulonglong2 v = w[j];
            acc[2 * j]     = fma2(aa, v.x, acc[2 * j]);
            acc[2 * j + 1] = fma2(aa, v.y, acc[2 * j + 1]);
        }
    }
    // phase 2: partner rows xb..xb+31, shuffled in chunks of 8
    const int xb = 32 - ob;
#pragma unroll
    for (int c = 0; c < 4; c++) {
        float rcv[8];
#pragma unroll
        for (int i = 0; i < 8; i++)
            rcv[i] = __shfl_xor_sync(0xFFFFFFFFu, own[c * 8 + i], 1);
#pragma unroll
        for (int i = 0; i < 8; i++) {
            ull aa = pack2(rcv[i]);
            const ulonglong2* w = reinterpret_cast<const ulonglong2*>(
                W + (xb + c * 8 + i) * HID + ob);
#pragma unroll
            for (int j = 0; j < 8; j++) {
                ulonglong2 v = w[j];
                acc[2 * j]     = fma2(aa, v.x, acc[2 * j]);
                acc[2 * j + 1] = fma2(aa, v.y, acc[2 * j + 1]);
            }
        }
    }
#pragma unroll
    for (int j = 0; j < 16; j++) {
        float2 v = unpack2(acc[j]);
        own[2 * j]     = lipswish(v.x);
        own[2 * j + 1] = lipswish(v.y);
    }
}

// Full MLP 4->64->64->64->4, pair-split. Both lanes of the pair hold y and
// both return the full 4-vector output (pair-reduced last layer).
// W layout: W1 @0 (256), W2 @256 (4096), W3 @4352 (4096), W4 @8448 (256)
// B layout: b1 @0, b2 @64, b3 @128, b4 @192
__device__ __forceinline__ float4 mlp_pair(const float* __restrict__ W,
                                           const float* __restrict__ B,
                                           float4 y, int ob) {
    float own[32];
    // layer 1 (K = 4), no shuffles: both lanes hold full y
    {
        ull acc[16];
        const ulonglong2* bb = reinterpret_cast<const ulonglong2*>(B + ob);
#pragma unroll
        for (int j = 0; j < 8; j++) {
            ulonglong2 b = bb[j];
            acc[2 * j] = b.x;
            acc[2 * j + 1] = b.y;
        }
        float in[4] = {y.x, y.y, y.z, y.w};
#pragma unroll
        for (int k = 0; k < 4; k++) {
            ull aa = pack2(in[k]);
            const ulonglong2* w =
                reinterpret_cast<const ulonglong2*>(W + k * HID + ob);
#pragma unroll
            for (int j = 0; j < 8; j++) {
                ulonglong2 v = w[j];
                acc[2 * j]     = fma2(aa, v.x, acc[2 * j]);
                acc[2 * j + 1] = fma2(aa, v.y, acc[2 * j + 1]);
            }
        }
#pragma unroll
        for (int j = 0; j < 16; j++) {
            float2 v = unpack2(acc[j]);
            own[2 * j]     = lipswish(v.x);
            own[2 * j + 1] = lipswish(v.y);
        }
    }
    dense64_pair(W + 256,        B + 64,  own, ob);
    dense64_pair(W + 256 + 4096, B + 128, own, ob);
    // layer 4 (64 -> 4): partial over this lane's 32 rows, then pair-reduce.
    ull o0 = 0, o1 = 0;
    const float* W4 = W + 256 + 8192;
#pragma unroll
    for (int i = 0; i < 32; i++) {
        ull aa = pack2(own[i]);
        ulonglong2 v =
            reinterpret_cast<const ulonglong2*>(W4 + (ob + i) * 4)[0];
        o0 = fma2(aa, v.x, o0);
        o1 = fma2(aa, v.y, o1);
    }
    o0 = add2(o0, __shfl_xor_sync(0xFFFFFFFFu, o0, 1));
    o1 = add2(o1, __shfl_xor_sync(0xFFFFFFFFu, o1, 1));
    const ulonglong2* b4 = reinterpret_cast<const ulonglong2*>(B + 192);
    ulonglong2 bo = b4[0];
    o0 = add2(o0, bo.x);
    o1 = add2(o1, bo.y);
    float2 lo = unpack2(o0), hi = unpack2(o1);
    return make_float4(lo.x, lo.y, hi.x, hi.y);
}

struct Params {
    const float* p[19];
    float* out;
};

// Shared layout (floats): sWf[8704] sWg[8704] sBf[196] sBg[196] sdt[511] ssq[511]
#define OFF_WG  8704
#define OFF_BF  17408
#define OFF_BG  17604
#define OFF_DT  17800
#define OFF_SQ  18311
#define SMEM_FLOATS 18824
#define SMEM_BYTES  (SMEM_FLOATS * 4)

__global__ __launch_bounds__(NTHR) void sde_kernel(Params P) {
    extern __shared__ float sm[];
    float* sWf = sm;
    float* sWg = sm + OFF_WG;
    float* sBf = sm + OFF_BF;
    float* sBg = sm + OFF_BG;
    float* sdt = sm + OFF_DT;
    float* ssq = sm + OFF_SQ;
    const int tid = threadIdx.x;

    // Stage parameters into shared memory.
    for (int i = tid; i < 256; i += NTHR) {
        sWf[i]        = P.p[3][i];
        sWf[8448 + i] = P.p[9][i];
        sWg[i]        = P.p[11][i];
        sWg[8448 + i] = P.p[17][i];
    }
    for (int i = tid; i < 4096; i += NTHR) {
        sWf[256 + i]  = P.p[5][i];
        sWf[4352 + i] = P.p[7][i];
        sWg[256 + i]  = P.p[13][i];
        sWg[4352 + i] = P.p[15][i];
    }
    for (int i = tid; i < HID; i += NTHR) {
        sBf[i]        = P.p[4][i];
        sBf[64 + i]   = P.p[6][i];
        sBf[128 + i]  = P.p[8][i];
        sBg[i]        = P.p[12][i];
        sBg[64 + i]   = P.p[14][i];
        sBg[128 + i]  = P.p[16][i];
    }
    if (tid < 4) {
        sBf[192 + tid] = P.p[10][tid];
        sBg[192 + tid] = P.p[18][tid];
    }
    for (int i = tid; i < TSTEPS - 1; i += NTHR) {
        float dt = P.p[1][i + 1] - P.p[1][i];
        sdt[i] = dt;
        ssq[i] = sqrtf(dt);
    }
    __syncthreads();

    const int gtid = blockIdx.x * NTHR + tid;
    const int n = gtid >> 1;          // sample index (2 threads per sample)
    const int p = gtid & 1;           // pair parity
    const int ob = p * 32;            // this lane's output-column base
    if (n >= NSMP) return;            // whole warps exit together (320 = 10 warps)

    const float4* y0 = (const float4*)P.p[0];
    const float4* nz = (const float4*)P.p[2];
    float4* out = (float4*)P.out;

    float4 y = y0[n];
    if (p == 0) out[n * TSTEPS] = y;  // t = 0

    for (int t = 0; t < TSTEPS - 1; t++) {
        float4 dw = __ldcs(&nz[t * NSMP + n]);
        float dt = sdt[t];
        float sq = ssq[t];

        float4 dr = mlp_pair(sWf, sBf, y, ob);  // drift net
        float4 dg = mlp_pair(sWg, sBg, y, ob);  // diffusion net

        float fx = fminf(fmaxf(dr.x, -100.0f), 100.0f);
        float fy = fminf(fmaxf(dr.y, -100.0f), 100.0f);
        float fz = fminf(fmaxf(dr.z, -100.0f), 100.0f);
        float fw = fminf(fmaxf(dr.w, -100.0f), 100.0f);

        float gx = fmaxf(softplus_acc(dg.x), 1e-4f);
        float gy = fmaxf(softplus_acc(dg.y), 1e-4f);
        float gz = fmaxf(softplus_acc(dg.z), 1e-4f);
        float gw = fmaxf(softplus_acc(dg.w), 1e-4f);

        y.x = y.x + fx * dt + gx * sq * dw.x;
        y.y = y.y + fy * dt + gy * sq * dw.y;
        y.z = y.z + fz * dt + gz * sq * dw.z;
        y.w = y.w + fw * dt + gw * sq * dw.w;

        if (p == 0) __stcs(&out[n * TSTEPS + t + 1], y);
    }
}

extern "C" void kernel_launch(void* const* d_in, const int* in_sizes, int n_in,
                              void* d_out, int out_size) {
    Params P;
    for (int i = 0; i < 19; i++) P.p[i] = (const float*)d_in[i];
    P.out = (float*)d_out;

    cudaFuncSetAttribute(sde_kernel, cudaFuncAttributeMaxDynamicSharedMemorySize,
                         SMEM_BYTES);
    sde_kernel<<<NCTA, NTHR, SMEM_BYTES>>>(P);
}

// round 6
// speedup vs baseline: 1.4645x; 1.4645x over previous
#include <cuda_runtime.h>

#define NSMP   32768
#define TSTEPS 512
#define HID    64
#define NTHR   448
#define HALF_T 224
#define NCTA   147   // 147*224 = 32928 >= 32768 samples; 14 warps/CTA, 1 CTA/SM

typedef unsigned long long ull;

// ---- packed f32x2 helpers (FFMA2 is PTX-only; ptxas never emits it from C++) ----
__device__ __forceinline__ ull fma2(ull a, ull b, ull c) {
    ull d;
    asm("fma.rn.f32x2 %0, %1, %2, %3;" : "=l"(d) : "l"(a), "l"(b), "l"(c));
    return d;
}
__device__ __forceinline__ ull pack2(float x) {
    ull d;
    asm("mov.b64 %0, {%1, %1};" : "=l"(d) : "f"(x));
    return d;
}
__device__ __forceinline__ float2 unpack2(ull v) {
    float lo, hi;
    asm("mov.b64 {%0, %1}, %2;" : "=f"(lo), "=f"(hi) : "l"(v));
    return make_float2(lo, hi);
}

__device__ __forceinline__ float lipswish(float x) {
    float s = __fdividef(1.0f, 1.0f + __expf(-x));
    return 0.909f * x * s;
}
__device__ __forceinline__ float softplus_acc(float x) {
    return fmaxf(x, 0.0f) + log1pf(__expf(-fabsf(x)));
}

// Half-output pass of a 64->64 dense layer: outputs [ob, ob+32) from h[64],
// lipswish applied, written to o[32]. Weights broadcast-loaded (all lanes of
// the warp read the same address). 16 packed accumulators live.
__device__ __forceinline__ void dense_half(const float* __restrict__ W,
                                           const float* __restrict__ B,
                                           const float (&h)[HID],
                                           float* __restrict__ o, int ob) {
    ull acc[16];
    const ulonglong2* bb = reinterpret_cast<const ulonglong2*>(B + ob);
#pragma unroll
    for (int j = 0; j < 8; j++) {
        ulonglong2 b = bb[j];
        acc[2 * j]     = b.x;
        acc[2 * j + 1] = b.y;
    }
#pragma unroll
    for (int k = 0; k < HID; k++) {
        ull aa = pack2(h[k]);
        const ulonglong2* w = reinterpret_cast<const ulonglong2*>(W + k * HID + ob);
#pragma unroll
        for (int j = 0; j < 8; j++) {
            ulonglong2 v = w[j];
            acc[2 * j]     = fma2(aa, v.x, acc[2 * j]);
            acc[2 * j + 1] = fma2(aa, v.y, acc[2 * j + 1]);
        }
    }
#pragma unroll
    for (int j = 0; j < 16; j++) {
        float2 v = unpack2(acc[j]);
        o[2 * j]     = lipswish(v.x);
        o[2 * j + 1] = lipswish(v.y);
    }
}

// Full MLP 4->64->64->64->4 with half-pass hidden layers.
// W layout: W1 @0 (256), W2 @256 (4096), W3 @4352 (4096), W4 @8448 (256)
// B layout: b1 @0, b2 @64, b3 @128, b4 @192
__device__ __forceinline__ float4 mlp(const float* __restrict__ W,
                                      const float* __restrict__ B,
                                      float4 y) {
    float h[HID];
    // layer 1 (K = 4): 32 packed accs, low pressure
    {
        ull acc[32];
        const ulonglong2* bb = reinterpret_cast<const ulonglong2*>(B);
#pragma unroll
        for (int j = 0; j < 16; j++) {
            ulonglong2 b = bb[j];
            acc[2 * j]     = b.x;
            acc[2 * j + 1] = b.y;
        }
        float in[4] = {y.x, y.y, y.z, y.w};
#pragma unroll
        for (int k = 0; k < 4; k++) {
            ull aa = pack2(in[k]);
            const ulonglong2* w = reinterpret_cast<const ulonglong2*>(W + k * HID);
#pragma unroll
            for (int j = 0; j < 16; j++) {
                ulonglong2 v = w[j];
                acc[2 * j]     = fma2(aa, v.x, acc[2 * j]);
                acc[2 * j + 1] = fma2(aa, v.y, acc[2 * j + 1]);
            }
        }
#pragma unroll
        for (int j = 0; j < 32; j++) {
            float2 v = unpack2(acc[j]);
            h[2 * j]     = lipswish(v.x);
            h[2 * j + 1] = lipswish(v.y);
        }
    }
    // layers 2 and 3: two half passes each (pass A buffers into ha, pass B
    // writes h[32..63] after all reads of h are done, then ha -> h[0..31])
    {
        float ha[32];
        dense_half(W + 256, B + 64, h, ha, 0);
        dense_half(W + 256, B + 64, h, h + 32, 32);
#pragma unroll
        for (int i = 0; i < 32; i++) h[i] = ha[i];
    }
    {
        float ha[32];
        dense_half(W + 256 + 4096, B + 128, h, ha, 0);
        dense_half(W + 256 + 4096, B + 128, h, h + 32, 32);
#pragma unroll
        for (int i = 0; i < 32; i++) h[i] = ha[i];
    }
    // layer 4 (64 -> 4), linear
    const ulonglong2* b4 = reinterpret_cast<const ulonglong2*>(B + 192);
    ulonglong2 bo = b4[0];
    ull o0 = bo.x, o1 = bo.y;
    const float* W4 = W + 256 + 8192;
#pragma unroll
    for (int k = 0; k < HID; k++) {
        ull aa = pack2(h[k]);
        ulonglong2 v = reinterpret_cast<const ulonglong2*>(W4 + k * 4)[0];
        o0 = fma2(aa, v.x, o0);
        o1 = fma2(aa, v.y, o1);
    }
    float2 lo = unpack2(o0), hi = unpack2(o1);
    return make_float4(lo.x, lo.y, hi.x, hi.y);
}

struct Params {
    const float* p[19];
    float* out;
};

// Shared layout (floats):
// sWf[8704] sWg[8704] sBf[196] sBg[196] sdt[511] ssq[511] pad sY[224*4] sG[224*4]
#define OFF_WG  8704
#define OFF_BF  17408
#define OFF_BG  17604
#define OFF_DT  17800
#define OFF_SQ  18311
#define OFF_Y   18824              // 16B aligned (18824 % 4 == 0)
#define OFF_G   (OFF_Y + HALF_T*4)
#define SMEM_FLOATS (OFF_G + HALF_T*4)
#define SMEM_BYTES  (SMEM_FLOATS * 4)

__global__ __launch_bounds__(NTHR, 1) void sde_kernel(Params P) {
    extern __shared__ float sm[];
    float* sWf = sm;
    float* sWg = sm + OFF_WG;
    float* sBf = sm + OFF_BF;
    float* sBg = sm + OFF_BG;
    float* sdt = sm + OFF_DT;
    float* ssq = sm + OFF_SQ;
    float4* sY = (float4*)(sm + OFF_Y);
    float4* sG = (float4*)(sm + OFF_G);
    const int tid = threadIdx.x;

    // Stage parameters into shared memory.
    // W layout per net: W1 @0 (256), W2 @256 (4096), W3 @4352 (4096), W4 @8448 (256)
    for (int i = tid; i < 256; i += NTHR) {
        sWf[i]        = P.p[3][i];
        sWf[8448 + i] = P.p[9][i];
        sWg[i]        = P.p[11][i];
        sWg[8448 + i] = P.p[17][i];
    }
    for (int i = tid; i < 4096; i += NTHR) {
        sWf[256 + i]  = P.p[5][i];
        sWf[4352 + i] = P.p[7][i];
        sWg[256 + i]  = P.p[13][i];
        sWg[4352 + i] = P.p[15][i];
    }
    for (int i = tid; i < HID; i += NTHR) {
        sBf[i]        = P.p[4][i];
        sBf[64 + i]   = P.p[6][i];
        sBf[128 + i]  = P.p[8][i];
        sBg[i]        = P.p[12][i];
        sBg[64 + i]   = P.p[14][i];
        sBg[128 + i]  = P.p[16][i];
    }
    if (tid < 4) {
        sBf[192 + tid] = P.p[10][tid];
        sBg[192 + tid] = P.p[18][tid];
    }
    for (int i = tid; i < TSTEPS - 1; i += NTHR) {
        float dt = P.p[1][i + 1] - P.p[1][i];
        sdt[i] = dt;
        ssq[i] = sqrtf(dt);
    }
    __syncthreads();

    // Warp-level net split: warps 0-6 (tid < 224) = drift net, warps 7-13 = diffusion.
    const bool isF = (tid < HALF_T);
    const int  s   = isF ? tid : tid - HALF_T;           // sample slot in CTA
    const int  n   = blockIdx.x * HALF_T + s;            // global sample
    const bool act = (n < NSMP);

    const float4* y0 = (const float4*)P.p[0];
    const float4* nz = (const float4*)P.p[2];
    float4* out = (float4*)P.out;

    float4 y = make_float4(0.f, 0.f, 0.f, 0.f);
    if (act && isF) {
        y = y0[n];
        out[n * TSTEPS] = y;   // t = 0
        sY[s] = y;
    }
    __syncthreads();

    for (int t = 0; t < TSTEPS - 1; t++) {
        float4 dr = make_float4(0.f, 0.f, 0.f, 0.f);
        float4 dw = make_float4(0.f, 0.f, 0.f, 0.f);
        if (act) {
            if (isF) {
                dw = __ldcs(&nz[t * NSMP + n]);          // stream noise early
                dr = mlp(sWf, sBf, y);                   // drift net on private y
            } else {
                float4 yg = sY[s];
                float4 dg = mlp(sWg, sBg, yg);           // diffusion net
                float4 g;
                g.x = fmaxf(softplus_acc(dg.x), 1e-4f);
                g.y = fmaxf(softplus_acc(dg.y), 1e-4f);
                g.z = fmaxf(softplus_acc(dg.z), 1e-4f);
                g.w = fmaxf(softplus_acc(dg.w), 1e-4f);
                sG[s] = g;
            }
        }
        __syncthreads();   // g published; f may now consume
        if (act && isF) {
            float4 g = sG[s];
            float dt = sdt[t];
            float sq = ssq[t];
            float fx = fminf(fmaxf(dr.x, -100.0f), 100.0f);
            float fy = fminf(fmaxf(dr.y, -100.0f), 100.0f);
            float fz = fminf(fmaxf(dr.z, -100.0f), 100.0f);
            float fw = fminf(fmaxf(dr.w, -100.0f), 100.0f);
            y.x = y.x + fx * dt + g.x * sq * dw.x;
            y.y = y.y + fy * dt + g.y * sq * dw.y;
            y.z = y.z + fz * dt + g.z * sq * dw.z;
            y.w = y.w + fw * dt + g.w * sq * dw.w;
            sY[s] = y;
            __stcs(&out[n * TSTEPS + t + 1], y);
        }
        __syncthreads();   // y published; sG free for next iteration
    }
}

extern "C" void kernel_launch(void* const* d_in, const int* in_sizes, int n_in,
                              void* d_out, int out_size) {
    Params P;
    for (int i = 0; i < 19; i++) P.p[i] = (const float*)d_in[i];
    P.out = (float*)d_out;

    cudaFuncSetAttribute(sde_kernel, cudaFuncAttributeMaxDynamicSharedMemorySize,
                         SMEM_BYTES);
    sde_kernel<<<NCTA, NTHR, SMEM_BYTES>>>(P);
}

// round 9
// speedup vs baseline: 5.1476x; 3.5149x over previous
#include <cuda_runtime.h>
#include <cstdint>

#define NSMP   32768
#define TSTEPS 512
#define NTHR   128
#define NCTA   256     // 256 CTAs x 4 warps x 32 samples = 32768

typedef unsigned int uint;

// ---------------- smem layout (32-bit word offsets) ----------------
#define OFF_DT 0        // 511 dt
#define OFF_SQ 512      // 511 sqrt(dt)
#define OFF_B  1024     // [net][256]: b1@0 b2@64 b3@128 b4pad@192(8)
#define OFF_W1 1536     // [net][half][nj][lane]          net stride 512, half 256
#define OFF_W4 2560     // [net][half][ktp][lane][4]      net stride 512, half 256
#define OFF_W2 3584     // [net][half][ktp][nj][lane][4]  net stride 4096, half 2048
#define OFF_W3 11776
#define SMEM_WORDS 19968
#define SMEM_BYTES (SMEM_WORDS * 4)

// ---------------- math helpers ----------------
__device__ __forceinline__ float lipswish(float x) {
    float s = __fdividef(1.0f, 1.0f + __expf(-x));
    return 0.909f * x * s;
}
__device__ __forceinline__ float softplus_acc(float x) {
    return fmaxf(x, 0.0f) + log1pf(__expf(-fabsf(x)));
}
// pack (x0, x1) -> hi bf16x2 (lower=x0) and lo (residual) bf16x2
__device__ __forceinline__ void split2(float x0, float x1, uint& h, uint& l) {
    asm("cvt.rn.bf16x2.f32 %0, %1, %2;" : "=r"(h) : "f"(x1), "f"(x0));
    float h0 = __uint_as_float(h << 16);
    float h1 = __uint_as_float(h & 0xFFFF0000u);
    asm("cvt.rn.bf16x2.f32 %0, %1, %2;" : "=r"(l) : "f"(x1 - h1), "f"(x0 - h0));
}

// ---------------- mma.sync wrappers (base sm_80+ PTX, OK on sm_103) ----------------
__device__ __forceinline__ void mma16(float* d, const uint* a, uint b0, uint b1) {
    asm("mma.sync.aligned.m16n8k16.row.col.f32.bf16.bf16.f32 "
        "{%0,%1,%2,%3},{%4,%5,%6,%7},{%8,%9},{%0,%1,%2,%3};"
        : "+f"(d[0]), "+f"(d[1]), "+f"(d[2]), "+f"(d[3])
        : "r"(a[0]), "r"(a[1]), "r"(a[2]), "r"(a[3]), "r"(b0), "r"(b1));
}
__device__ __forceinline__ void mma8(float* d, uint a0, uint a1, uint b0) {
    asm("mma.sync.aligned.m16n8k8.row.col.f32.bf16.bf16.f32 "
        "{%0,%1,%2,%3},{%4,%5},{%6},{%0,%1,%2,%3};"
        : "+f"(d[0]), "+f"(d[1]), "+f"(d[2]), "+f"(d[3])
        : "r"(a0), "r"(a1), "r"(b0));
}

// D fragment (m16n8 per nj) -> lipswish -> bf16 split -> A fragments of next layer.
// Mapping: nj even -> a0/a1 of kt=nj/2, nj odd -> a2/a3.
__device__ __forceinline__ void epilogue(float d[2][8][4],
                                         uint Ahi[2][4][4], uint Alo[2][4][4]) {
#pragma unroll
    for (int mi = 0; mi < 2; mi++)
#pragma unroll
        for (int nj = 0; nj < 8; nj++) {
            float a0 = lipswish(d[mi][nj][0]);
            float a1 = lipswish(d[mi][nj][1]);
            float a2 = lipswish(d[mi][nj][2]);
            float a3 = lipswish(d[mi][nj][3]);
            uint h01, l01, h23, l23;
            split2(a0, a1, h01, l01);
            split2(a2, a3, h23, l23);
            int kt = nj >> 1;
            if ((nj & 1) == 0) {
                Ahi[mi][kt][0] = h01; Alo[mi][kt][0] = l01;
                Ahi[mi][kt][1] = h23; Alo[mi][kt][1] = l23;
            } else {
                Ahi[mi][kt][2] = h01; Alo[mi][kt][2] = l01;
                Ahi[mi][kt][3] = h23; Alo[mi][kt][3] = l23;
            }
        }
}

// 64->64 hidden layer: A (bf16-split regs) x W-frags(smem) -> D -> epilogue -> A
__device__ __forceinline__ void hidden(const uint* __restrict__ usm, int wbase,
                                       const float* __restrict__ bias,
                                       uint Ahi[2][4][4], uint Alo[2][4][4],
                                       int lane, int tig) {
    float d[2][8][4];
#pragma unroll
    for (int nj = 0; nj < 8; nj++) {
        float2 b = *(const float2*)(bias + nj * 8 + 2 * tig);
#pragma unroll
        for (int mi = 0; mi < 2; mi++) {
            d[mi][nj][0] = b.x; d[mi][nj][1] = b.y;
            d[mi][nj][2] = b.x; d[mi][nj][3] = b.y;
        }
    }
#pragma unroll
    for (int ktp = 0; ktp < 2; ktp++)
#pragma unroll
        for (int nj = 0; nj < 8; nj++) {
            int pos = ((ktp * 8 + nj) * 32 + lane) * 4;
            uint4 wh = *(const uint4*)(usm + wbase + pos);
            uint4 wl = *(const uint4*)(usm + wbase + 2048 + pos);
#pragma unroll
            for (int mi = 0; mi < 2; mi++) {
                mma16(d[mi][nj], Ahi[mi][2 * ktp],     wh.x, wh.y);
                mma16(d[mi][nj], Ahi[mi][2 * ktp],     wl.x, wl.y);
                mma16(d[mi][nj], Alo[mi][2 * ktp],     wh.x, wh.y);
                mma16(d[mi][nj], Ahi[mi][2 * ktp + 1], wh.z, wh.w);
                mma16(d[mi][nj], Ahi[mi][2 * ktp + 1], wl.z, wl.w);
                mma16(d[mi][nj], Alo[mi][2 * ktp + 1], wh.z, wh.w);
            }
        }
    epilogue(d, Ahi, Alo);
}

// Full MLP for one net: y(frag, split) -> d4[8] (two m16n8 D-frags, cols 0-3 valid)
__device__ __forceinline__ void net_eval(const uint* __restrict__ usm,
                                         const float* __restrict__ smf, int net,
                                         const uint yhi[2][2], const uint ylo[2][2],
                                         float* __restrict__ d4, int lane, int tig) {
    const float* bias = smf + OFF_B + net * 256;
    uint Ahi[2][4][4], Alo[2][4][4];
    // ---- L1: m16n8k8, K=4 padded to 8 ----
    {
        float d1[2][8][4];
#pragma unroll
        for (int nj = 0; nj < 8; nj++) {
            float2 b = *(const float2*)(bias + nj * 8 + 2 * tig);
#pragma unroll
            for (int mi = 0; mi < 2; mi++) {
                d1[mi][nj][0] = b.x; d1[mi][nj][1] = b.y;
                d1[mi][nj][2] = b.x; d1[mi][nj][3] = b.y;
            }
        }
        int w1 = OFF_W1 + net * 512;
#pragma unroll
        for (int nj = 0; nj < 8; nj++) {
            uint wh = usm[w1 + nj * 32 + lane];
            uint wl = usm[w1 + 256 + nj * 32 + lane];
#pragma unroll
            for (int mi = 0; mi < 2; mi++) {
                mma8(d1[mi][nj], yhi[mi][0], yhi[mi][1], wh);
                mma8(d1[mi][nj], yhi[mi][0], yhi[mi][1], wl);
                mma8(d1[mi][nj], ylo[mi][0], ylo[mi][1], wh);
            }
        }
        epilogue(d1, Ahi, Alo);
    }
    hidden(usm, OFF_W2 + net * 4096, bias + 64,  Ahi, Alo, lane, tig);
    hidden(usm, OFF_W3 + net * 4096, bias + 128, Ahi, Alo, lane, tig);
    // ---- L4: m16n8k16, N=4 padded to 8 ----
    {
        float2 bb = *(const float2*)(bias + 192 + 2 * tig);
        d4[0] = bb.x; d4[1] = bb.y; d4[2] = bb.x; d4[3] = bb.y;
        d4[4] = bb.x; d4[5] = bb.y; d4[6] = bb.x; d4[7] = bb.y;
        int w4 = OFF_W4 + net * 512;
#pragma unroll
        for (int ktp = 0; ktp < 2; ktp++) {
            int pos = (ktp * 32 + lane) * 4;
            uint4 wh = *(const uint4*)(usm + w4 + pos);
            uint4 wl = *(const uint4*)(usm + w4 + 256 + pos);
#pragma unroll
            for (int mi = 0; mi < 2; mi++) {
                mma16(d4 + mi * 4, Ahi[mi][2 * ktp],     wh.x, wh.y);
                mma16(d4 + mi * 4, Ahi[mi][2 * ktp],     wl.x, wl.y);
                mma16(d4 + mi * 4, Alo[mi][2 * ktp],     wh.x, wh.y);
                mma16(d4 + mi * 4, Ahi[mi][2 * ktp + 1], wh.z, wh.w);
                mma16(d4 + mi * 4, Ahi[mi][2 * ktp + 1], wl.z, wl.w);
                mma16(d4 + mi * 4, Alo[mi][2 * ktp + 1], wh.z, wh.w);
            }
        }
    }
}

struct Params {
    const float* p[19];
    float* out;
};

__global__ __launch_bounds__(NTHR, 2) void sde_kernel(Params P) {
    extern __shared__ float smf[];
    uint* usm = (uint*)smf;
    const int tid = threadIdx.x;

    // ---------------- staging ----------------
    for (int i = tid; i < TSTEPS - 1; i += NTHR) {
        float dt = P.p[1][i + 1] - P.p[1][i];
        smf[OFF_DT + i] = dt;
        smf[OFF_SQ + i] = sqrtf(dt);
    }
    // biases (b4 padded to 8 with zeros)
    {
        const int bsrc[8] = {4, 6, 8, 10, 12, 14, 16, 18};
        for (int net = 0; net < 2; net++)
            for (int a = 0; a < 4; a++) {
                int cnt = (a < 3) ? 64 : 8;
                const float* src = P.p[bsrc[net * 4 + a]];
                for (int i = tid; i < cnt; i += NTHR)
                    smf[OFF_B + net * 256 + a * 64 + i] =
                        (a < 3 || i < 4) ? src[i] : 0.0f;
            }
    }
    // W2/W3 fragment-linear staging
    {
        const float* Ws[4] = {P.p[5], P.p[13], P.p[7], P.p[15]};
        const int    bs[4] = {OFF_W2, OFF_W2 + 4096, OFF_W3, OFF_W3 + 4096};
        for (int nl = 0; nl < 4; nl++) {
            const float* S = Ws[nl];
            int base = bs[nl];
            for (int idx = tid; idx < 2048; idx += NTHR) {
                int w = idx & 3, lane = (idx >> 2) & 31;
                int nj = (idx >> 7) & 7, ktp = idx >> 10;
                int g = lane >> 2, tg = lane & 3;
                int kt = ktp * 2 + (w >> 1), breg = w & 1;
                int n = nj * 8 + g;
                int k0 = kt * 16 + 2 * tg + 8 * breg;
                uint hi, lo;
                split2(S[k0 * 64 + n], S[(k0 + 1) * 64 + n], hi, lo);
                usm[base + idx] = hi;
                usm[base + 2048 + idx] = lo;
            }
        }
    }
    // W1 staging (K padded 4->8)
    {
        const float* W1s[2] = {P.p[3], P.p[11]};
        for (int net = 0; net < 2; net++)
            for (int idx = tid; idx < 256; idx += NTHR) {
                int lane = idx & 31, nj = idx >> 5;
                int g = lane >> 2, tg = lane & 3;
                int n = nj * 8 + g;
                int k0 = 2 * tg;
                float v0 = (k0 < 4)     ? W1s[net][k0 * 64 + n]       : 0.0f;
                float v1 = (k0 + 1 < 4) ? W1s[net][(k0 + 1) * 64 + n] : 0.0f;
                uint hi, lo;
                split2(v0, v1, hi, lo);
                usm[OFF_W1 + net * 512 + idx] = hi;
                usm[OFF_W1 + net * 512 + 256 + idx] = lo;
            }
    }
    // W4 staging (N padded 4->8)
    {
        const float* W4s[2] = {P.p[9], P.p[17]};
        for (int net = 0; net < 2; net++)
            for (int idx = tid; idx < 256; idx += NTHR) {
                int w = idx & 3, lane = (idx >> 2) & 31, ktp = idx >> 7;
                int g = lane >> 2, tg = lane & 3;
                int kt = ktp * 2 + (w >> 1), breg = w & 1;
                int n = g;
                int k0 = kt * 16 + 2 * tg + 8 * breg;
                float v0 = (n < 4) ? W4s[net][k0 * 4 + n]       : 0.0f;
                float v1 = (n < 4) ? W4s[net][(k0 + 1) * 4 + n] : 0.0f;
                uint hi, lo;
                split2(v0, v1, hi, lo);
                usm[OFF_W4 + net * 512 + idx] = hi;
                usm[OFF_W4 + net * 512 + 256 + idx] = lo;
            }
    }
    __syncthreads();

    // ---------------- per-warp fragment-domain SDE loop ----------------
    const int lane = tid & 31;
    const int g = lane >> 2, tig = lane & 3;
    const int gw = blockIdx.x * 4 + (tid >> 5);
    const int sbase = gw * 32;
    const bool ldok = (tig < 2);

    const float* y0 = P.p[0];
    const float* nz = P.p[2];
    float* out = P.out;

    // y in D4-fragment form: y[mi][0..3] = rows (16mi+g, +8) x cols (2tig, 2tig+1)
    float y[2][4];
#pragma unroll
    for (int mi = 0; mi < 2; mi++) {
        int r0 = sbase + mi * 16 + g;
        if (ldok) {
            float2 v0 = *(const float2*)(y0 + r0 * 4 + 2 * tig);
            float2 v1 = *(const float2*)(y0 + (r0 + 8) * 4 + 2 * tig);
            y[mi][0] = v0.x; y[mi][1] = v0.y; y[mi][2] = v1.x; y[mi][3] = v1.y;
            *(float2*)(out + (size_t)r0 * TSTEPS * 4 + 2 * tig) = v0;
            *(float2*)(out + (size_t)(r0 + 8) * TSTEPS * 4 + 2 * tig) = v1;
        } else {
            y[mi][0] = y[mi][1] = y[mi][2] = y[mi][3] = 0.0f;
        }
    }
    uint yhi[2][2], ylo[2][2];
#pragma unroll
    for (int mi = 0; mi < 2; mi++) {
        split2(y[mi][0], y[mi][1], yhi[mi][0], ylo[mi][0]);
        split2(y[mi][2], y[mi][3], yhi[mi][1], ylo[mi][1]);
    }

    for (int t = 0; t < TSTEPS - 1; t++) {
        float dwv[2][4];
#pragma unroll
        for (int mi = 0; mi < 2; mi++) {
            if (ldok) {
                int r0 = sbase + mi * 16 + g;
                const float* b = nz + ((size_t)t * NSMP) * 4;
                float2 v0 = *(const float2*)(b + r0 * 4 + 2 * tig);
                float2 v1 = *(const float2*)(b + (r0 + 8) * 4 + 2 * tig);
                dwv[mi][0] = v0.x; dwv[mi][1] = v0.y;
                dwv[mi][2] = v1.x; dwv[mi][3] = v1.y;
            } else {
                dwv[mi][0] = dwv[mi][1] = dwv[mi][2] = dwv[mi][3] = 0.0f;
            }
        }

        float df[8], dg[8];
        net_eval(usm, smf, 0, yhi, ylo, df, lane, tig);
        net_eval(usm, smf, 1, yhi, ylo, dg, lane, tig);

        float dt = smf[OFF_DT + t];
        float sq = smf[OFF_SQ + t];

#pragma unroll
        for (int mi = 0; mi < 2; mi++)
#pragma unroll
            for (int j = 0; j < 4; j++) {
                float f = fminf(fmaxf(df[mi * 4 + j], -100.0f), 100.0f);
                float gg = fmaxf(softplus_acc(dg[mi * 4 + j]), 1e-4f);
                y[mi][j] = y[mi][j] + f * dt + gg * sq * dwv[mi][j];
            }

#pragma unroll
        for (int mi = 0; mi < 2; mi++) {
            if (ldok) {
                int r0 = sbase + mi * 16 + g;
                *(float2*)(out + ((size_t)r0 * TSTEPS + t + 1) * 4 + 2 * tig) =
                    make_float2(y[mi][0], y[mi][1]);
                *(float2*)(out + ((size_t)(r0 + 8) * TSTEPS + t + 1) * 4 + 2 * tig) =
                    make_float2(y[mi][2], y[mi][3]);
            }
            split2(y[mi][0], y[mi][1], yhi[mi][0], ylo[mi][0]);
            split2(y[mi][2], y[mi][3], yhi[mi][1], ylo[mi][1]);
        }
    }
}

extern "C" void kernel_launch(void* const* d_in, const int* in_sizes, int n_in,
                              void* d_out, int out_size) {
    Params P;
    for (int i = 0; i < 19; i++) P.p[i] = (const float*)d_in[i];
    P.out = (float*)d_out;

    cudaFuncSetAttribute(sde_kernel, cudaFuncAttributeMaxDynamicSharedMemorySize,
                         SMEM_BYTES);
    sde_kernel<<<NCTA, NTHR, SMEM_BYTES>>>(P);
}

// round 10
// speedup vs baseline: 5.8173x; 1.1301x over previous
#include <cuda_runtime.h>
#include <cstdint>

#define NSMP   32768
#define TSTEPS 512
#define NTHR   224      // 7 warps/CTA
#define NCTA   147      // 147 CTAs x 7 warps x 32 samples = 32928 slots >= 32768

typedef unsigned int uint;

// ---------------- smem layout (32-bit word offsets) ----------------
#define OFF_DT 0        // 511 dt
#define OFF_SQ 512      // 511 sqrt(dt)
#define OFF_B  1024     // [net][256]: b1@0 b2@64 b3@128 b4pad@192(8)
#define OFF_W1 1536     // [net][half][nj][lane]          net stride 512, half 256
#define OFF_W4 2560     // [net][half][ktp][lane][4]      net stride 512, half 256
#define OFF_W2 3584     // [net][half][ktp][nj][lane][4]  net stride 4096, half 2048
#define OFF_W3 11776
#define SMEM_WORDS 19968
#define SMEM_BYTES (SMEM_WORDS * 4)

// ---------------- math helpers ----------------
// lipswish = 0.909*x*sigmoid(x); sigmoid(x) = 0.5 + 0.5*tanh(x/2)
// -> 0.4545*x*(1 + tanh(0.5x)): 1 MUFU + 2 ops (was ex2+rcp+3 ops)
__device__ __forceinline__ float lipswish(float x) {
    float t;
    asm("tanh.approx.f32 %0, %1;" : "=f"(t) : "f"(0.5f * x));
    return 0.4545f * x * (1.0f + t);
}
__device__ __forceinline__ float softplus_acc(float x) {
    return fmaxf(x, 0.0f) + log1pf(__expf(-fabsf(x)));
}
// pack (x0, x1) -> hi bf16x2 (lower=x0) and lo (residual) bf16x2
__device__ __forceinline__ void split2(float x0, float x1, uint& h, uint& l) {
    asm("cvt.rn.bf16x2.f32 %0, %1, %2;" : "=r"(h) : "f"(x1), "f"(x0));
    float h0 = __uint_as_float(h << 16);
    float h1 = __uint_as_float(h & 0xFFFF0000u);
    asm("cvt.rn.bf16x2.f32 %0, %1, %2;" : "=r"(l) : "f"(x1 - h1), "f"(x0 - h0));
}

// ---------------- mma.sync wrappers (base sm_80+ PTX, OK on sm_103) ----------------
__device__ __forceinline__ void mma16(float* d, const uint* a, uint b0, uint b1) {
    asm("mma.sync.aligned.m16n8k16.row.col.f32.bf16.bf16.f32 "
        "{%0,%1,%2,%3},{%4,%5,%6,%7},{%8,%9},{%0,%1,%2,%3};"
        : "+f"(d[0]), "+f"(d[1]), "+f"(d[2]), "+f"(d[3])
        : "r"(a[0]), "r"(a[1]), "r"(a[2]), "r"(a[3]), "r"(b0), "r"(b1));
}
__device__ __forceinline__ void mma8(float* d, uint a0, uint a1, uint b0) {
    asm("mma.sync.aligned.m16n8k8.row.col.f32.bf16.bf16.f32 "
        "{%0,%1,%2,%3},{%4,%5},{%6},{%0,%1,%2,%3};"
        : "+f"(d[0]), "+f"(d[1]), "+f"(d[2]), "+f"(d[3])
        : "r"(a0), "r"(a1), "r"(b0));
}

// D fragment (m16n8 per nj) -> lipswish -> bf16 split -> A fragments of next layer.
// Mapping: nj even -> a0/a1 of kt=nj/2, nj odd -> a2/a3.
__device__ __forceinline__ void epilogue(float d[2][8][4],
                                         uint Ahi[2][4][4], uint Alo[2][4][4]) {
#pragma unroll
    for (int mi = 0; mi < 2; mi++)
#pragma unroll
        for (int nj = 0; nj < 8; nj++) {
            float a0 = lipswish(d[mi][nj][0]);
            float a1 = lipswish(d[mi][nj][1]);
            float a2 = lipswish(d[mi][nj][2]);
            float a3 = lipswish(d[mi][nj][3]);
            uint h01, l01, h23, l23;
            split2(a0, a1, h01, l01);
            split2(a2, a3, h23, l23);
            int kt = nj >> 1;
            if ((nj & 1) == 0) {
                Ahi[mi][kt][0] = h01; Alo[mi][kt][0] = l01;
                Ahi[mi][kt][1] = h23; Alo[mi][kt][1] = l23;
            } else {
                Ahi[mi][kt][2] = h01; Alo[mi][kt][2] = l01;
                Ahi[mi][kt][3] = h23; Alo[mi][kt][3] = l23;
            }
        }
}

// 64->64 hidden layer: A (bf16-split regs) x W-frags(smem) -> D -> epilogue -> A
__device__ __forceinline__ void hidden(const uint* __restrict__ usm, int wbase,
                                       const float* __restrict__ bias,
                                       uint Ahi[2][4][4], uint Alo[2][4][4],
                                       int lane, int tig) {
    float d[2][8][4];
#pragma unroll
    for (int nj = 0; nj < 8; nj++) {
        float2 b = *(const float2*)(bias + nj * 8 + 2 * tig);
#pragma unroll
        for (int mi = 0; mi < 2; mi++) {
            d[mi][nj][0] = b.x; d[mi][nj][1] = b.y;
            d[mi][nj][2] = b.x; d[mi][nj][3] = b.y;
        }
    }
#pragma unroll
    for (int ktp = 0; ktp < 2; ktp++)
#pragma unroll
        for (int nj = 0; nj < 8; nj++) {
            int pos = ((ktp * 8 + nj) * 32 + lane) * 4;
            uint4 wh = *(const uint4*)(usm + wbase + pos);
            uint4 wl = *(const uint4*)(usm + wbase + 2048 + pos);
#pragma unroll
            for (int mi = 0; mi < 2; mi++) {
                mma16(d[mi][nj], Ahi[mi][2 * ktp],     wh.x, wh.y);
                mma16(d[mi][nj], Ahi[mi][2 * ktp],     wl.x, wl.y);
                mma16(d[mi][nj], Alo[mi][2 * ktp],     wh.x, wh.y);
                mma16(d[mi][nj], Ahi[mi][2 * ktp + 1], wh.z, wh.w);
                mma16(d[mi][nj], Ahi[mi][2 * ktp + 1], wl.z, wl.w);
                mma16(d[mi][nj], Alo[mi][2 * ktp + 1], wh.z, wh.w);
            }
        }
    epilogue(d, Ahi, Alo);
}

// Full MLP for one net: y(frag, split) -> d4[8] (two m16n8 D-frags, cols 0-3 valid)
__device__ __forceinline__ void net_eval(const uint* __restrict__ usm,
                                         const float* __restrict__ smf, int net,
                                         const uint yhi[2][2], const uint ylo[2][2],
                                         float* __restrict__ d4, int lane, int tig) {
    const float* bias = smf + OFF_B + net * 256;
    uint Ahi[2][4][4], Alo[2][4][4];
    // ---- L1: m16n8k8, K=4 padded to 8 ----
    {
        float d1[2][8][4];
#pragma unroll
        for (int nj = 0; nj < 8; nj++) {
            float2 b = *(const float2*)(bias + nj * 8 + 2 * tig);
#pragma unroll
            for (int mi = 0; mi < 2; mi++) {
                d1[mi][nj][0] = b.x; d1[mi][nj][1] = b.y;
                d1[mi][nj][2] = b.x; d1[mi][nj][3] = b.y;
            }
        }
        int w1 = OFF_W1 + net * 512;
#pragma unroll
        for (int nj = 0; nj < 8; nj++) {
            uint wh = usm[w1 + nj * 32 + lane];
            uint wl = usm[w1 + 256 + nj * 32 + lane];
#pragma unroll
            for (int mi = 0; mi < 2; mi++) {
                mma8(d1[mi][nj], yhi[mi][0], yhi[mi][1], wh);
                mma8(d1[mi][nj], yhi[mi][0], yhi[mi][1], wl);
                mma8(d1[mi][nj], ylo[mi][0], ylo[mi][1], wh);
            }
        }
        epilogue(d1, Ahi, Alo);
    }
    hidden(usm, OFF_W2 + net * 4096, bias + 64,  Ahi, Alo, lane, tig);
    hidden(usm, OFF_W3 + net * 4096, bias + 128, Ahi, Alo, lane, tig);
    // ---- L4: m16n8k16, N=4 padded to 8 ----
    {
        float2 bb = *(const float2*)(bias + 192 + 2 * tig);
        d4[0] = bb.x; d4[1] = bb.y; d4[2] = bb.x; d4[3] = bb.y;
        d4[4] = bb.x; d4[5] = bb.y; d4[6] = bb.x; d4[7] = bb.y;
        int w4 = OFF_W4 + net * 512;
#pragma unroll
        for (int ktp = 0; ktp < 2; ktp++) {
            int pos = (ktp * 32 + lane) * 4;
            uint4 wh = *(const uint4*)(usm + w4 + pos);
            uint4 wl = *(const uint4*)(usm + w4 + 256 + pos);
#pragma unroll
            for (int mi = 0; mi < 2; mi++) {
                mma16(d4 + mi * 4, Ahi[mi][2 * ktp],     wh.x, wh.y);
                mma16(d4 + mi * 4, Ahi[mi][2 * ktp],     wl.x, wl.y);
                mma16(d4 + mi * 4, Alo[mi][2 * ktp],     wh.x, wh.y);
                mma16(d4 + mi * 4, Ahi[mi][2 * ktp + 1], wh.z, wh.w);
                mma16(d4 + mi * 4, Ahi[mi][2 * ktp + 1], wl.z, wl.w);
                mma16(d4 + mi * 4, Alo[mi][2 * ktp + 1], wh.z, wh.w);
            }
        }
    }
}

struct Params {
    const float* p[19];
    float* out;
};

__global__ __launch_bounds__(NTHR, 1) void sde_kernel(Params P) {
    extern __shared__ float smf[];
    uint* usm = (uint*)smf;
    const int tid = threadIdx.x;

    // ---------------- staging ----------------
    for (int i = tid; i < TSTEPS - 1; i += NTHR) {
        float dt = P.p[1][i + 1] - P.p[1][i];
        smf[OFF_DT + i] = dt;
        smf[OFF_SQ + i] = sqrtf(dt);
    }
    // biases (b4 padded to 8 with zeros)
    {
        const int bsrc[8] = {4, 6, 8, 10, 12, 14, 16, 18};
        for (int net = 0; net < 2; net++)
            for (int a = 0; a < 4; a++) {
                int cnt = (a < 3) ? 64 : 8;
                const float* src = P.p[bsrc[net * 4 + a]];
                for (int i = tid; i < cnt; i += NTHR)
                    smf[OFF_B + net * 256 + a * 64 + i] =
                        (a < 3 || i < 4) ? src[i] : 0.0f;
            }
    }
    // W2/W3 fragment-linear staging
    {
        const float* Ws[4] = {P.p[5], P.p[13], P.p[7], P.p[15]};
        const int    bs[4] = {OFF_W2, OFF_W2 + 4096, OFF_W3, OFF_W3 + 4096};
        for (int nl = 0; nl < 4; nl++) {
            const float* S = Ws[nl];
            int base = bs[nl];
            for (int idx = tid; idx < 2048; idx += NTHR) {
                int w = idx & 3, lane = (idx >> 2) & 31;
                int nj = (idx >> 7) & 7, ktp = idx >> 10;
                int g = lane >> 2, tg = lane & 3;
                int kt = ktp * 2 + (w >> 1), breg = w & 1;
                int n = nj * 8 + g;
                int k0 = kt * 16 + 2 * tg + 8 * breg;
                uint hi, lo;
                split2(S[k0 * 64 + n], S[(k0 + 1) * 64 + n], hi, lo);
                usm[base + idx] = hi;
                usm[base + 2048 + idx] = lo;
            }
        }
    }
    // W1 staging (K padded 4->8)
    {
        const float* W1s[2] = {P.p[3], P.p[11]};
        for (int net = 0; net < 2; net++)
            for (int idx = tid; idx < 256; idx += NTHR) {
                int lane = idx & 31, nj = idx >> 5;
                int g = lane >> 2, tg = lane & 3;
                int n = nj * 8 + g;
                int k0 = 2 * tg;
                float v0 = (k0 < 4)     ? W1s[net][k0 * 64 + n]       : 0.0f;
                float v1 = (k0 + 1 < 4) ? W1s[net][(k0 + 1) * 64 + n] : 0.0f;
                uint hi, lo;
                split2(v0, v1, hi, lo);
                usm[OFF_W1 + net * 512 + idx] = hi;
                usm[OFF_W1 + net * 512 + 256 + idx] = lo;
            }
    }
    // W4 staging (N padded 4->8)
    {
        const float* W4s[2] = {P.p[9], P.p[17]};
        for (int net = 0; net < 2; net++)
            for (int idx = tid; idx < 256; idx += NTHR) {
                int w = idx & 3, lane = (idx >> 2) & 31, ktp = idx >> 7;
                int g = lane >> 2, tg = lane & 3;
                int kt = ktp * 2 + (w >> 1), breg = w & 1;
                int n = g;
                int k0 = kt * 16 + 2 * tg + 8 * breg;
                float v0 = (n < 4) ? W4s[net][k0 * 4 + n]       : 0.0f;
                float v1 = (n < 4) ? W4s[net][(k0 + 1) * 4 + n] : 0.0f;
                uint hi, lo;
                split2(v0, v1, hi, lo);
                usm[OFF_W4 + net * 512 + idx] = hi;
                usm[OFF_W4 + net * 512 + 256 + idx] = lo;
            }
    }
    __syncthreads();

    // ---------------- per-warp fragment-domain SDE loop ----------------
    const int lane = tid & 31;
    const int g = lane >> 2, tig = lane & 3;
    const int gw = blockIdx.x * (NTHR / 32) + (tid >> 5);
    const int sbase = gw * 32;
    if (sbase >= NSMP) return;          // tail warps (5 of 1029) exit whole
    const bool ldok = (tig < 2);

    const float* y0 = P.p[0];
    const float* nz = P.p[2];
    float* out = P.out;

    // y in D4-fragment form: y[mi][0..3] = rows (16mi+g, +8) x cols (2tig, 2tig+1)
    float y[2][4];
#pragma unroll
    for (int mi = 0; mi < 2; mi++) {
        int r0 = sbase + mi * 16 + g;
        if (ldok) {
            float2 v0 = *(const float2*)(y0 + r0 * 4 + 2 * tig);
            float2 v1 = *(const float2*)(y0 + (r0 + 8) * 4 + 2 * tig);
            y[mi][0] = v0.x; y[mi][1] = v0.y; y[mi][2] = v1.x; y[mi][3] = v1.y;
            *(float2*)(out + (size_t)r0 * TSTEPS * 4 + 2 * tig) = v0;
            *(float2*)(out + (size_t)(r0 + 8) * TSTEPS * 4 + 2 * tig) = v1;
        } else {
            y[mi][0] = y[mi][1] = y[mi][2] = y[mi][3] = 0.0f;
        }
    }
    uint yhi[2][2], ylo[2][2];
#pragma unroll
    for (int mi = 0; mi < 2; mi++) {
        split2(y[mi][0], y[mi][1], yhi[mi][0], ylo[mi][0]);
        split2(y[mi][2], y[mi][3], yhi[mi][1], ylo[mi][1]);
    }

    for (int t = 0; t < TSTEPS - 1; t++) {
        float dwv[2][4];
#pragma unroll
        for (int mi = 0; mi < 2; mi++) {
            if (ldok) {
                int r0 = sbase + mi * 16 + g;
                const float* b = nz + ((size_t)t * NSMP) * 4;
                float2 v0 = *(const float2*)(b + r0 * 4 + 2 * tig);
                float2 v1 = *(const float2*)(b + (r0 + 8) * 4 + 2 * tig);
                dwv[mi][0] = v0.x; dwv[mi][1] = v0.y;
                dwv[mi][2] = v1.x; dwv[mi][3] = v1.y;
            } else {
                dwv[mi][0] = dwv[mi][1] = dwv[mi][2] = dwv[mi][3] = 0.0f;
            }
        }

        float df[8], dg[8];
        net_eval(usm, smf, 0, yhi, ylo, df, lane, tig);
        net_eval(usm, smf, 1, yhi, ylo, dg, lane, tig);

        float dt = smf[OFF_DT + t];
        float sq = smf[OFF_SQ + t];

#pragma unroll
        for (int mi = 0; mi < 2; mi++)
#pragma unroll
            for (int j = 0; j < 4; j++) {
                float f = fminf(fmaxf(df[mi * 4 + j], -100.0f), 100.0f);
                float gg = fmaxf(softplus_acc(dg[mi * 4 + j]), 1e-4f);
                y[mi][j] = y[mi][j] + f * dt + gg * sq * dwv[mi][j];
            }

#pragma unroll
        for (int mi = 0; mi < 2; mi++) {
            if (ldok) {
                int r0 = sbase + mi * 16 + g;
                *(float2*)(out + ((size_t)r0 * TSTEPS + t + 1) * 4 + 2 * tig) =
                    make_float2(y[mi][0], y[mi][1]);
                *(float2*)(out + ((size_t)(r0 + 8) * TSTEPS + t + 1) * 4 + 2 * tig) =
                    make_float2(y[mi][2], y[mi][3]);
            }
            split2(y[mi][0], y[mi][1], yhi[mi][0], ylo[mi][0]);
            split2(y[mi][2], y[mi][3], yhi[mi][1], ylo[mi][1]);
        }
    }
}

extern "C" void kernel_launch(void* const* d_in, const int* in_sizes, int n_in,
                              void* d_out, int out_size) {
    Params P;
    for (int i = 0; i < 19; i++) P.p[i] = (const float*)d_in[i];
    P.out = (float*)d_out;

    cudaFuncSetAttribute(sde_kernel, cudaFuncAttributeMaxDynamicSharedMemorySize,
                         SMEM_BYTES);
    sde_kernel<<<NCTA, NTHR, SMEM_BYTES>>>(P);
}

// round 11
// speedup vs baseline: 6.1434x; 1.0561x over previous
#include <cuda_runtime.h>
#include <cstdint>

#define NSMP   32768
#define TSTEPS 512
#define NTHR   224      // 7 warps/CTA
#define NCTA   293      // 293*7 = 2051 warps x 16 samples >= 32768; 2 CTAs/SM

typedef unsigned int uint;

// ---------------- smem layout (32-bit word offsets) ----------------
#define OFF_DT 0        // 511 dt
#define OFF_SQ 512      // 511 sqrt(dt)
#define OFF_B  1024     // [net][256]: b1@0 b2@64 b3@128 b4pad@192(8)
#define OFF_W1 1536     // [net][half][nj][lane]          net stride 512, half 256
#define OFF_W4 2560     // [net][half][ktp][lane][4]      net stride 512, half 256
#define OFF_W2 3584     // [net][half][ktp][nj][lane][4]  net stride 4096, half 2048
#define OFF_W3 11776
#define SMEM_WORDS 19968
#define SMEM_BYTES (SMEM_WORDS * 4)

// ---------------- math helpers ----------------
// lipswish = 0.909*x*sigmoid(x) = 0.4545*x*(1 + tanh(0.5x)): 1 MUFU + 2 ops
__device__ __forceinline__ float lipswish(float x) {
    float t;
    asm("tanh.approx.f32 %0, %1;" : "=f"(t) : "f"(0.5f * x));
    return 0.4545f * x * (1.0f + t);
}
__device__ __forceinline__ float softplus_acc(float x) {
    return fmaxf(x, 0.0f) + log1pf(__expf(-fabsf(x)));
}
// pack (x0, x1) -> hi bf16x2 (lower=x0) and lo (residual) bf16x2
__device__ __forceinline__ void split2(float x0, float x1, uint& h, uint& l) {
    asm("cvt.rn.bf16x2.f32 %0, %1, %2;" : "=r"(h) : "f"(x1), "f"(x0));
    float h0 = __uint_as_float(h << 16);
    float h1 = __uint_as_float(h & 0xFFFF0000u);
    asm("cvt.rn.bf16x2.f32 %0, %1, %2;" : "=r"(l) : "f"(x1 - h1), "f"(x0 - h0));
}

// ---------------- mma.sync wrappers (base sm_80+ PTX, OK on sm_103) ----------------
__device__ __forceinline__ void mma16(float* d, const uint* a, uint b0, uint b1) {
    asm("mma.sync.aligned.m16n8k16.row.col.f32.bf16.bf16.f32 "
        "{%0,%1,%2,%3},{%4,%5,%6,%7},{%8,%9},{%0,%1,%2,%3};"
        : "+f"(d[0]), "+f"(d[1]), "+f"(d[2]), "+f"(d[3])
        : "r"(a[0]), "r"(a[1]), "r"(a[2]), "r"(a[3]), "r"(b0), "r"(b1));
}
__device__ __forceinline__ void mma8(float* d, uint a0, uint a1, uint b0) {
    asm("mma.sync.aligned.m16n8k8.row.col.f32.bf16.bf16.f32 "
        "{%0,%1,%2,%3},{%4,%5},{%6},{%0,%1,%2,%3};"
        : "+f"(d[0]), "+f"(d[1]), "+f"(d[2]), "+f"(d[3])
        : "r"(a0), "r"(a1), "r"(b0));
}

// D fragments (8 x m16n8) -> lipswish -> bf16 split -> A fragments of next layer.
// Mapping: nj even -> a0/a1 of kt=nj/2, nj odd -> a2/a3.
__device__ __forceinline__ void epilogue(float d[8][4],
                                         uint Ahi[4][4], uint Alo[4][4]) {
#pragma unroll
    for (int nj = 0; nj < 8; nj++) {
        float a0 = lipswish(d[nj][0]);
        float a1 = lipswish(d[nj][1]);
        float a2 = lipswish(d[nj][2]);
        float a3 = lipswish(d[nj][3]);
        uint h01, l01, h23, l23;
        split2(a0, a1, h01, l01);
        split2(a2, a3, h23, l23);
        int kt = nj >> 1;
        if ((nj & 1) == 0) {
            Ahi[kt][0] = h01; Alo[kt][0] = l01;
            Ahi[kt][1] = h23; Alo[kt][1] = l23;
        } else {
            Ahi[kt][2] = h01; Alo[kt][2] = l01;
            Ahi[kt][3] = h23; Alo[kt][3] = l23;
        }
    }
}

// 64->64 hidden layer (M=16): A (bf16-split regs) x W-frags(smem) -> D -> epi -> A
__device__ __forceinline__ void hidden(const uint* __restrict__ usm, int wbase,
                                       const float* __restrict__ bias,
                                       uint Ahi[4][4], uint Alo[4][4],
                                       int lane, int tig) {
    float d[8][4];
#pragma unroll
    for (int nj = 0; nj < 8; nj++) {
        float2 b = *(const float2*)(bias + nj * 8 + 2 * tig);
        d[nj][0] = b.x; d[nj][1] = b.y; d[nj][2] = b.x; d[nj][3] = b.y;
    }
#pragma unroll
    for (int ktp = 0; ktp < 2; ktp++)
#pragma unroll
        for (int nj = 0; nj < 8; nj++) {
            int pos = ((ktp * 8 + nj) * 32 + lane) * 4;
            uint4 wh = *(const uint4*)(usm + wbase + pos);
            uint4 wl = *(const uint4*)(usm + wbase + 2048 + pos);
            mma16(d[nj], Ahi[2 * ktp],     wh.x, wh.y);
            mma16(d[nj], Ahi[2 * ktp],     wl.x, wl.y);
            mma16(d[nj], Alo[2 * ktp],     wh.x, wh.y);
            mma16(d[nj], Ahi[2 * ktp + 1], wh.z, wh.w);
            mma16(d[nj], Ahi[2 * ktp + 1], wl.z, wl.w);
            mma16(d[nj], Alo[2 * ktp + 1], wh.z, wh.w);
        }
    epilogue(d, Ahi, Alo);
}

// Full MLP for one net (M=16): y(frag, split) -> d4[4] (one m16n8 D-frag, cols 0-3)
__device__ __forceinline__ void net_eval(const uint* __restrict__ usm,
                                         const float* __restrict__ smf, int net,
                                         const uint yhi[2], const uint ylo[2],
                                         float* __restrict__ d4, int lane, int tig) {
    const float* bias = smf + OFF_B + net * 256;
    uint Ahi[4][4], Alo[4][4];
    // ---- L1: m16n8k8, K=4 padded to 8 ----
    {
        float d1[8][4];
#pragma unroll
        for (int nj = 0; nj < 8; nj++) {
            float2 b = *(const float2*)(bias + nj * 8 + 2 * tig);
            d1[nj][0] = b.x; d1[nj][1] = b.y; d1[nj][2] = b.x; d1[nj][3] = b.y;
        }
        int w1 = OFF_W1 + net * 512;
#pragma unroll
        for (int nj = 0; nj < 8; nj++) {
            uint wh = usm[w1 + nj * 32 + lane];
            uint wl = usm[w1 + 256 + nj * 32 + lane];
            mma8(d1[nj], yhi[0], yhi[1], wh);
            mma8(d1[nj], yhi[0], yhi[1], wl);
            mma8(d1[nj], ylo[0], ylo[1], wh);
        }
        epilogue(d1, Ahi, Alo);
    }
    hidden(usm, OFF_W2 + net * 4096, bias + 64,  Ahi, Alo, lane, tig);
    hidden(usm, OFF_W3 + net * 4096, bias + 128, Ahi, Alo, lane, tig);
    // ---- L4: m16n8k16, N=4 padded to 8 ----
    {
        float2 bb = *(const float2*)(bias + 192 + 2 * tig);
        d4[0] = bb.x; d4[1] = bb.y; d4[2] = bb.x; d4[3] = bb.y;
        int w4 = OFF_W4 + net * 512;
#pragma unroll
        for (int ktp = 0; ktp < 2; ktp++) {
            int pos = (ktp * 32 + lane) * 4;
            uint4 wh = *(const uint4*)(usm + w4 + pos);
            uint4 wl = *(const uint4*)(usm + w4 + 256 + pos);
            mma16(d4, Ahi[2 * ktp],     wh.x, wh.y);
            mma16(d4, Ahi[2 * ktp],     wl.x, wl.y);
            mma16(d4, Alo[2 * ktp],     wh.x, wh.y);
            mma16(d4, Ahi[2 * ktp + 1], wh.z, wh.w);
            mma16(d4, Ahi[2 * ktp + 1], wl.z, wl.w);
            mma16(d4, Alo[2 * ktp + 1], wh.z, wh.w);
        }
    }
}

struct Params {
    const float* p[19];
    float* out;
};

__global__ __launch_bounds__(NTHR, 2) void sde_kernel(Params P) {
    extern __shared__ float smf[];
    uint* usm = (uint*)smf;
    const int tid = threadIdx.x;

    // ---------------- staging ----------------
    for (int i = tid; i < TSTEPS - 1; i += NTHR) {
        float dt = P.p[1][i + 1] - P.p[1][i];
        smf[OFF_DT + i] = dt;
        smf[OFF_SQ + i] = sqrtf(dt);
    }
    // biases (b4 padded to 8 with zeros)
    {
        const int bsrc[8] = {4, 6, 8, 10, 12, 14, 16, 18};
        for (int net = 0; net < 2; net++)
            for (int a = 0; a < 4; a++) {
                int cnt = (a < 3) ? 64 : 8;
                const float* src = P.p[bsrc[net * 4 + a]];
                for (int i = tid; i < cnt; i += NTHR)
                    smf[OFF_B + net * 256 + a * 64 + i] =
                        (a < 3 || i < 4) ? src[i] : 0.0f;
            }
    }
    // W2/W3 fragment-linear staging
    {
        const float* Ws[4] = {P.p[5], P.p[13], P.p[7], P.p[15]};
        const int    bs[4] = {OFF_W2, OFF_W2 + 4096, OFF_W3, OFF_W3 + 4096};
        for (int nl = 0; nl < 4; nl++) {
            const float* S = Ws[nl];
            int base = bs[nl];
            for (int idx = tid; idx < 2048; idx += NTHR) {
                int w = idx & 3, lane = (idx >> 2) & 31;
                int nj = (idx >> 7) & 7, ktp = idx >> 10;
                int g = lane >> 2, tg = lane & 3;
                int kt = ktp * 2 + (w >> 1), breg = w & 1;
                int n = nj * 8 + g;
                int k0 = kt * 16 + 2 * tg + 8 * breg;
                uint hi, lo;
                split2(S[k0 * 64 + n], S[(k0 + 1) * 64 + n], hi, lo);
                usm[base + idx] = hi;
                usm[base + 2048 + idx] = lo;
            }
        }
    }
    // W1 staging (K padded 4->8)
    {
        const float* W1s[2] = {P.p[3], P.p[11]};
        for (int net = 0; net < 2; net++)
            for (int idx = tid; idx < 256; idx += NTHR) {
                int lane = idx & 31, nj = idx >> 5;
                int g = lane >> 2, tg = lane & 3;
                int n = nj * 8 + g;
                int k0 = 2 * tg;
                float v0 = (k0 < 4)     ? W1s[net][k0 * 64 + n]       : 0.0f;
                float v1 = (k0 + 1 < 4) ? W1s[net][(k0 + 1) * 64 + n] : 0.0f;
                uint hi, lo;
                split2(v0, v1, hi, lo);
                usm[OFF_W1 + net * 512 + idx] = hi;
                usm[OFF_W1 + net * 512 + 256 + idx] = lo;
            }
    }
    // W4 staging (N padded 4->8)
    {
        const float* W4s[2] = {P.p[9], P.p[17]};
        for (int net = 0; net < 2; net++)
            for (int idx = tid; idx < 256; idx += NTHR) {
                int w = idx & 3, lane = (idx >> 2) & 31, ktp = idx >> 7;
                int g = lane >> 2, tg = lane & 3;
                int kt = ktp * 2 + (w >> 1), breg = w & 1;
                int n = g;
                int k0 = kt * 16 + 2 * tg + 8 * breg;
                float v0 = (n < 4) ? W4s[net][k0 * 4 + n]       : 0.0f;
                float v1 = (n < 4) ? W4s[net][(k0 + 1) * 4 + n] : 0.0f;
                uint hi, lo;
                split2(v0, v1, hi, lo);
                usm[OFF_W4 + net * 512 + idx] = hi;
                usm[OFF_W4 + net * 512 + 256 + idx] = lo;
            }
    }
    __syncthreads();

    // ---------------- per-warp fragment-domain SDE loop (16 samples/warp) ----------------
    const int lane = tid & 31;
    const int g = lane >> 2, tig = lane & 3;
    const int gw = blockIdx.x * (NTHR / 32) + (tid >> 5);
    const int sbase = gw * 16;
    if (sbase >= NSMP) return;          // tail warps (3 of 2051) exit whole
    const bool ldok = (tig < 2);

    const float* y0 = P.p[0];
    const float* nz = P.p[2];
    float* out = P.out;

    // y in D-fragment form: y[0..3] = rows (sbase+g, +8) x cols (2tig, 2tig+1)
    float y[4];
    const int r0 = sbase + g;
    if (ldok) {
        float2 v0 = *(const float2*)(y0 + r0 * 4 + 2 * tig);
        float2 v1 = *(const float2*)(y0 + (r0 + 8) * 4 + 2 * tig);
        y[0] = v0.x; y[1] = v0.y; y[2] = v1.x; y[3] = v1.y;
        *(float2*)(out + (size_t)r0 * TSTEPS * 4 + 2 * tig) = v0;
        *(float2*)(out + (size_t)(r0 + 8) * TSTEPS * 4 + 2 * tig) = v1;
    } else {
        y[0] = y[1] = y[2] = y[3] = 0.0f;
    }
    uint yhi[2], ylo[2];
    split2(y[0], y[1], yhi[0], ylo[0]);
    split2(y[2], y[3], yhi[1], ylo[1]);

    for (int t = 0; t < TSTEPS - 1; t++) {
        float dwv[4];
        if (ldok) {
            const float* b = nz + ((size_t)t * NSMP) * 4;
            float2 v0 = *(const float2*)(b + r0 * 4 + 2 * tig);
            float2 v1 = *(const float2*)(b + (r0 + 8) * 4 + 2 * tig);
            dwv[0] = v0.x; dwv[1] = v0.y; dwv[2] = v1.x; dwv[3] = v1.y;
        } else {
            dwv[0] = dwv[1] = dwv[2] = dwv[3] = 0.0f;
        }

        float df[4], dg[4];
        net_eval(usm, smf, 0, yhi, ylo, df, lane, tig);
        net_eval(usm, smf, 1, yhi, ylo, dg, lane, tig);

        float dt = smf[OFF_DT + t];
        float sq = smf[OFF_SQ + t];

#pragma unroll
        for (int j = 0; j < 4; j++) {
            float f = fminf(fmaxf(df[j], -100.0f), 100.0f);
            float gg = fmaxf(softplus_acc(dg[j]), 1e-4f);
            y[j] = y[j] + f * dt + gg * sq * dwv[j];
        }

        if (ldok) {
            *(float2*)(out + ((size_t)r0 * TSTEPS + t + 1) * 4 + 2 * tig) =
                make_float2(y[0], y[1]);
            *(float2*)(out + ((size_t)(r0 + 8) * TSTEPS + t + 1) * 4 + 2 * tig) =
                make_float2(y[2], y[3]);
        }
        split2(y[0], y[1], yhi[0], ylo[0]);
        split2(y[2], y[3], yhi[1], ylo[1]);
    }
}

extern "C" void kernel_launch(void* const* d_in, const int* in_sizes, int n_in,
                              void* d_out, int out_size) {
    Params P;
    for (int i = 0; i < 19; i++) P.p[i] = (const float*)d_in[i];
    P.out = (float*)d_out;

    cudaFuncSetAttribute(sde_kernel, cudaFuncAttributeMaxDynamicSharedMemorySize,
                         SMEM_BYTES);
    sde_kernel<<<NCTA, NTHR, SMEM_BYTES>>>(P);
}

// round 12
// speedup vs baseline: 9.0436x; 1.4721x over previous
#include <cuda_runtime.h>
#include <cstdint>

#define NSMP   32768
#define TSTEPS 512
#define NTHR   224      // 7 warps/CTA
#define NCTA   293      // 293*7 = 2051 warps x 16 samples >= 32768; 2 CTAs/SM

typedef unsigned int uint;

// ---------------- smem layout (32-bit word offsets) ----------------
#define OFF_DT 0        // 511 dt
#define OFF_SQ 512      // 511 sqrt(dt)
#define OFF_B  1024     // [net][256]: b1@0 b2@64 b3@128 b4pad@192(8)
#define OFF_W1 1536     // [net][half][nj][lane]          net stride 512, half 256
#define OFF_W4 2560     // [net][half][ktp][lane][4]      net stride 512, half 256
#define OFF_W2 3584     // [net][half][ktp][nj][lane][4]  net stride 4096, half 2048
#define OFF_W3 11776
#define SMEM_WORDS 19968
#define SMEM_BYTES (SMEM_WORDS * 4)

// ---------------- math helpers ----------------
// lipswish = 0.909*x*sigmoid(x) = 0.4545*x*(1 + tanh(0.5x)): 1 MUFU + 3 ops
__device__ __forceinline__ float lipswish(float x) {
    float t;
    asm("tanh.approx.f32 %0, %1;" : "=f"(t) : "f"(0.5f * x));
    return 0.4545f * x * (1.0f + t);
}
__device__ __forceinline__ float softplus_acc(float x) {
    return fmaxf(x, 0.0f) + log1pf(__expf(-fabsf(x)));
}
// pack (x0, x1) -> single bf16x2 (lower=x0)
__device__ __forceinline__ uint pack_bf16x2(float x0, float x1) {
    uint h;
    asm("cvt.rn.bf16x2.f32 %0, %1, %2;" : "=r"(h) : "f"(x1), "f"(x0));
    return h;
}
// pack (x0, x1) -> hi bf16x2 (lower=x0) and lo (residual) bf16x2 (used for y & weights)
__device__ __forceinline__ void split2(float x0, float x1, uint& h, uint& l) {
    asm("cvt.rn.bf16x2.f32 %0, %1, %2;" : "=r"(h) : "f"(x1), "f"(x0));
    float h0 = __uint_as_float(h << 16);
    float h1 = __uint_as_float(h & 0xFFFF0000u);
    asm("cvt.rn.bf16x2.f32 %0, %1, %2;" : "=r"(l) : "f"(x1 - h1), "f"(x0 - h0));
}

// ---------------- mma.sync wrappers (base sm_80+ PTX, OK on sm_103) ----------------
__device__ __forceinline__ void mma16(float* d, const uint* a, uint b0, uint b1) {
    asm("mma.sync.aligned.m16n8k16.row.col.f32.bf16.bf16.f32 "
        "{%0,%1,%2,%3},{%4,%5,%6,%7},{%8,%9},{%0,%1,%2,%3};"
        : "+f"(d[0]), "+f"(d[1]), "+f"(d[2]), "+f"(d[3])
        : "r"(a[0]), "r"(a[1]), "r"(a[2]), "r"(a[3]), "r"(b0), "r"(b1));
}
__device__ __forceinline__ void mma8(float* d, uint a0, uint a1, uint b0) {
    asm("mma.sync.aligned.m16n8k8.row.col.f32.bf16.bf16.f32 "
        "{%0,%1,%2,%3},{%4,%5},{%6},{%0,%1,%2,%3};"
        : "+f"(d[0]), "+f"(d[1]), "+f"(d[2]), "+f"(d[3])
        : "r"(a0), "r"(a1), "r"(b0));
}

// D fragments (8 x m16n8) -> lipswish -> bf16 (hi only) -> A fragments of next layer.
// Weights keep the hi/lo split (A·Bh + A·Bl = A x full-precision W), so only the
// activation is quantized to bf16 (anchored error model: rel_err ~2-5e-4).
__device__ __forceinline__ void epilogue(float d[8][4], uint Ahi[4][4]) {
#pragma unroll
    for (int nj = 0; nj < 8; nj++) {
        float a0 = lipswish(d[nj][0]);
        float a1 = lipswish(d[nj][1]);
        float a2 = lipswish(d[nj][2]);
        float a3 = lipswish(d[nj][3]);
        uint h01 = pack_bf16x2(a0, a1);
        uint h23 = pack_bf16x2(a2, a3);
        int kt = nj >> 1;
        if ((nj & 1) == 0) {
            Ahi[kt][0] = h01;
            Ahi[kt][1] = h23;
        } else {
            Ahi[kt][2] = h01;
            Ahi[kt][3] = h23;
        }
    }
}

// 64->64 hidden layer (M=16): A(bf16) x W(hi+lo) -> D -> epilogue -> A
__device__ __forceinline__ void hidden(const uint* __restrict__ usm, int wbase,
                                       const float* __restrict__ bias,
                                       uint Ahi[4][4], int lane, int tig) {
    float d[8][4];
#pragma unroll
    for (int nj = 0; nj < 8; nj++) {
        float2 b = *(const float2*)(bias + nj * 8 + 2 * tig);
        d[nj][0] = b.x; d[nj][1] = b.y; d[nj][2] = b.x; d[nj][3] = b.y;
    }
#pragma unroll
    for (int ktp = 0; ktp < 2; ktp++)
#pragma unroll
        for (int nj = 0; nj < 8; nj++) {
            int pos = ((ktp * 8 + nj) * 32 + lane) * 4;
            uint4 wh = *(const uint4*)(usm + wbase + pos);
            uint4 wl = *(const uint4*)(usm + wbase + 2048 + pos);
            mma16(d[nj], Ahi[2 * ktp],     wh.x, wh.y);
            mma16(d[nj], Ahi[2 * ktp],     wl.x, wl.y);
            mma16(d[nj], Ahi[2 * ktp + 1], wh.z, wh.w);
            mma16(d[nj], Ahi[2 * ktp + 1], wl.z, wl.w);
        }
    epilogue(d, Ahi);
}

// Full MLP for one net (M=16): y(frag, split) -> d4[4] (one m16n8 D-frag, cols 0-3)
// L1 keeps the 3-product split (y precision seeds everything; only 8 extra mma8).
__device__ __forceinline__ void net_eval(const uint* __restrict__ usm,
                                         const float* __restrict__ smf, int net,
                                         const uint yhi[2], const uint ylo[2],
                                         float* __restrict__ d4, int lane, int tig) {
    const float* bias = smf + OFF_B + net * 256;
    uint Ahi[4][4];
    // ---- L1: m16n8k8, K=4 padded to 8 ----
    {
        float d1[8][4];
#pragma unroll
        for (int nj = 0; nj < 8; nj++) {
            float2 b = *(const float2*)(bias + nj * 8 + 2 * tig);
            d1[nj][0] = b.x; d1[nj][1] = b.y; d1[nj][2] = b.x; d1[nj][3] = b.y;
        }
        int w1 = OFF_W1 + net * 512;
#pragma unroll
        for (int nj = 0; nj < 8; nj++) {
            uint wh = usm[w1 + nj * 32 + lane];
            uint wl = usm[w1 + 256 + nj * 32 + lane];
            mma8(d1[nj], yhi[0], yhi[1], wh);
            mma8(d1[nj], yhi[0], yhi[1], wl);
            mma8(d1[nj], ylo[0], ylo[1], wh);
        }
        epilogue(d1, Ahi);
    }
    hidden(usm, OFF_W2 + net * 4096, bias + 64,  Ahi, lane, tig);
    hidden(usm, OFF_W3 + net * 4096, bias + 128, Ahi, lane, tig);
    // ---- L4: m16n8k16, N=4 padded to 8 ----
    {
        float2 bb = *(const float2*)(bias + 192 + 2 * tig);
        d4[0] = bb.x; d4[1] = bb.y; d4[2] = bb.x; d4[3] = bb.y;
        int w4 = OFF_W4 + net * 512;
#pragma unroll
        for (int ktp = 0; ktp < 2; ktp++) {
            int pos = (ktp * 32 + lane) * 4;
            uint4 wh = *(const uint4*)(usm + w4 + pos);
            uint4 wl = *(const uint4*)(usm + w4 + 256 + pos);
            mma16(d4, Ahi[2 * ktp],     wh.x, wh.y);
            mma16(d4, Ahi[2 * ktp],     wl.x, wl.y);
            mma16(d4, Ahi[2 * ktp + 1], wh.z, wh.w);
            mma16(d4, Ahi[2 * ktp + 1], wl.z, wl.w);
        }
    }
}

struct Params {
    const float* p[19];
    float* out;
};

__global__ __launch_bounds__(NTHR, 2) void sde_kernel(Params P) {
    extern __shared__ float smf[];
    uint* usm = (uint*)smf;
    const int tid = threadIdx.x;

    // ---------------- staging ----------------
    for (int i = tid; i < TSTEPS - 1; i += NTHR) {
        float dt = P.p[1][i + 1] - P.p[1][i];
        smf[OFF_DT + i] = dt;
        smf[OFF_SQ + i] = sqrtf(dt);
    }
    // biases (b4 padded to 8 with zeros)
    {
        const int bsrc[8] = {4, 6, 8, 10, 12, 14, 16, 18};
        for (int net = 0; net < 2; net++)
            for (int a = 0; a < 4; a++) {
                int cnt = (a < 3) ? 64 : 8;
                const float* src = P.p[bsrc[net * 4 + a]];
                for (int i = tid; i < cnt; i += NTHR)
                    smf[OFF_B + net * 256 + a * 64 + i] =
                        (a < 3 || i < 4) ? src[i] : 0.0f;
            }
    }
    // W2/W3 fragment-linear staging (hi/lo split)
    {
        const float* Ws[4] = {P.p[5], P.p[13], P.p[7], P.p[15]};
        const int    bs[4] = {OFF_W2, OFF_W2 + 4096, OFF_W3, OFF_W3 + 4096};
        for (int nl = 0; nl < 4; nl++) {
            const float* S = Ws[nl];
            int base = bs[nl];
            for (int idx = tid; idx < 2048; idx += NTHR) {
                int w = idx & 3, lane = (idx >> 2) & 31;
                int nj = (idx >> 7) & 7, ktp = idx >> 10;
                int g = lane >> 2, tg = lane & 3;
                int kt = ktp * 2 + (w >> 1), breg = w & 1;
                int n = nj * 8 + g;
                int k0 = kt * 16 + 2 * tg + 8 * breg;
                uint hi, lo;
                split2(S[k0 * 64 + n], S[(k0 + 1) * 64 + n], hi, lo);
                usm[base + idx] = hi;
                usm[base + 2048 + idx] = lo;
            }
        }
    }
    // W1 staging (K padded 4->8)
    {
        const float* W1s[2] = {P.p[3], P.p[11]};
        for (int net = 0; net < 2; net++)
            for (int idx = tid; idx < 256; idx += NTHR) {
                int lane = idx & 31, nj = idx >> 5;
                int g = lane >> 2, tg = lane & 3;
                int n = nj * 8 + g;
                int k0 = 2 * tg;
                float v0 = (k0 < 4)     ? W1s[net][k0 * 64 + n]       : 0.0f;
                float v1 = (k0 + 1 < 4) ? W1s[net][(k0 + 1) * 64 + n] : 0.0f;
                uint hi, lo;
                split2(v0, v1, hi, lo);
                usm[OFF_W1 + net * 512 + idx] = hi;
                usm[OFF_W1 + net * 512 + 256 + idx] = lo;
            }
    }
    // W4 staging (N padded 4->8)
    {
        const float* W4s[2] = {P.p[9], P.p[17]};
        for (int net = 0; net < 2; net++)
            for (int idx = tid; idx < 256; idx += NTHR) {
                int w = idx & 3, lane = (idx >> 2) & 31, ktp = idx >> 7;
                int g = lane >> 2, tg = lane & 3;
                int kt = ktp * 2 + (w >> 1), breg = w & 1;
                int n = g;
                int k0 = kt * 16 + 2 * tg + 8 * breg;
                float v0 = (n < 4) ? W4s[net][k0 * 4 + n]       : 0.0f;
                float v1 = (n < 4) ? W4s[net][(k0 + 1) * 4 + n] : 0.0f;
                uint hi, lo;
                split2(v0, v1, hi, lo);
                usm[OFF_W4 + net * 512 + idx] = hi;
                usm[OFF_W4 + net * 512 + 256 + idx] = lo;
            }
    }
    __syncthreads();

    // ---------------- per-warp fragment-domain SDE loop (16 samples/warp) ----------------
    const int lane = tid & 31;
    const int g = lane >> 2, tig = lane & 3;
    const int gw = blockIdx.x * (NTHR / 32) + (tid >> 5);
    const int sbase = gw * 16;
    if (sbase >= NSMP) return;          // tail warps (3 of 2051) exit whole
    const bool ldok = (tig < 2);

    const float* y0 = P.p[0];
    const float* nz = P.p[2];
    float* out = P.out;

    // y in D-fragment form: y[0..3] = rows (sbase+g, +8) x cols (2tig, 2tig+1)
    float y[4];
    const int r0 = sbase + g;
    if (ldok) {
        float2 v0 = *(const float2*)(y0 + r0 * 4 + 2 * tig);
        float2 v1 = *(const float2*)(y0 + (r0 + 8) * 4 + 2 * tig);
        y[0] = v0.x; y[1] = v0.y; y[2] = v1.x; y[3] = v1.y;
        *(float2*)(out + (size_t)r0 * TSTEPS * 4 + 2 * tig) = v0;
        *(float2*)(out + (size_t)(r0 + 8) * TSTEPS * 4 + 2 * tig) = v1;
    } else {
        y[0] = y[1] = y[2] = y[3] = 0.0f;
    }
    uint yhi[2], ylo[2];
    split2(y[0], y[1], yhi[0], ylo[0]);
    split2(y[2], y[3], yhi[1], ylo[1]);

    for (int t = 0; t < TSTEPS - 1; t++) {
        float dwv[4];
        if (ldok) {
            const float* b = nz + ((size_t)t * NSMP) * 4;
            float2 v0 = *(const float2*)(b + r0 * 4 + 2 * tig);
            float2 v1 = *(const float2*)(b + (r0 + 8) * 4 + 2 * tig);
            dwv[0] = v0.x; dwv[1] = v0.y; dwv[2] = v1.x; dwv[3] = v1.y;
        } else {
            dwv[0] = dwv[1] = dwv[2] = dwv[3] = 0.0f;
        }

        float df[4], dg[4];
        net_eval(usm, smf, 0, yhi, ylo, df, lane, tig);
        net_eval(usm, smf, 1, yhi, ylo, dg, lane, tig);

        float dt = smf[OFF_DT + t];
        float sq = smf[OFF_SQ + t];

#pragma unroll
        for (int j = 0; j < 4; j++) {
            float f = fminf(fmaxf(df[j], -100.0f), 100.0f);
            float gg = fmaxf(softplus_acc(dg[j]), 1e-4f);
            y[j] = y[j] + f * dt + gg * sq * dwv[j];
        }

        if (ldok) {
            *(float2*)(out + ((size_t)r0 * TSTEPS + t + 1) * 4 + 2 * tig) =
                make_float2(y[0], y[1]);
            *(float2*)(out + ((size_t)(r0 + 8) * TSTEPS + t + 1) * 4 + 2 * tig) =
                make_float2(y[2], y[3]);
        }
        split2(y[0], y[1], yhi[0], ylo[0]);
        split2(y[2], y[3], yhi[1], ylo[1]);
    }
}

extern "C" void kernel_launch(void* const* d_in, const int* in_sizes, int n_in,
                              void* d_out, int out_size) {
    Params P;
    for (int i = 0; i < 19; i++) P.p[i] = (const float*)d_in[i];
    P.out = (float*)d_out;

    cudaFuncSetAttribute(sde_kernel, cudaFuncAttributeMaxDynamicSharedMemorySize,
                         SMEM_BYTES);
    sde_kernel<<<NCTA, NTHR, SMEM_BYTES>>>(P);
}

// round 16
// speedup vs baseline: 12.3906x; 1.3701x over previous
#include <cuda_runtime.h>
#include <cstdint>

#define NSMP   32768
#define TSTEPS 512
#define NTHR   224      // 7 warps/CTA
#define NCTA   293      // 293*7 = 2051 warps x 16 samples >= 32768; 2 CTAs/SM

typedef unsigned int uint;

// ---------------- smem layout (32-bit word offsets) ----------------
#define OFF_DT 0        // 511 dt
#define OFF_SQ 512      // 511 sqrt(dt)
#define OFF_B  1024     // [net][256]: b1@0 b2@64 b3@128 b4pad@192(8)
#define OFF_W1 1536     // [net][half][nj][lane]          net stride 512 (hi+lo)
#define OFF_W4 2560     // [net][half][ktp][lane][4]      net stride 512 (hi+lo)
#define OFF_W2 3584     // [net][ktp][nj][lane][4]        net stride 2048 (hi only)
#define OFF_W3 7680
#define SMEM_WORDS 11776
#define SMEM_BYTES (SMEM_WORDS * 4)

// ---------------- math helpers ----------------
// lipswish = 0.909*x*sigmoid(x) = 0.4545*x*(1 + tanh(0.5x)): 1 MUFU + 3 ops
__device__ __forceinline__ float lipswish(float x) {
    float t;
    asm("tanh.approx.f32 %0, %1;" : "=f"(t) : "f"(0.5f * x));
    return 0.4545f * x * (1.0f + t);
}
__device__ __forceinline__ float softplus_acc(float x) {
    return fmaxf(x, 0.0f) + log1pf(__expf(-fabsf(x)));
}
// pack (x0, x1) -> single bf16x2 (lower=x0)
__device__ __forceinline__ uint pack_bf16x2(float x0, float x1) {
    uint h;
    asm("cvt.rn.bf16x2.f32 %0, %1, %2;" : "=r"(h) : "f"(x1), "f"(x0));
    return h;
}
// pack (x0, x1) -> hi bf16x2 (lower=x0) and lo (residual) bf16x2 (y, W1, W4)
__device__ __forceinline__ void split2(float x0, float x1, uint& h, uint& l) {
    asm("cvt.rn.bf16x2.f32 %0, %1, %2;" : "=r"(h) : "f"(x1), "f"(x0));
    float h0 = __uint_as_float(h << 16);
    float h1 = __uint_as_float(h & 0xFFFF0000u);
    asm("cvt.rn.bf16x2.f32 %0, %1, %2;" : "=r"(l) : "f"(x1 - h1), "f"(x0 - h0));
}

// ---------------- mma.sync wrappers (base sm_80+ PTX, OK on sm_103) ----------------
__device__ __forceinline__ void mma16(float* d, const uint* a, uint b0, uint b1) {
    asm("mma.sync.aligned.m16n8k16.row.col.f32.bf16.bf16.f32 "
        "{%0,%1,%2,%3},{%4,%5,%6,%7},{%8,%9},{%0,%1,%2,%3};"
        : "+f"(d[0]), "+f"(d[1]), "+f"(d[2]), "+f"(d[3])
        : "r"(a[0]), "r"(a[1]), "r"(a[2]), "r"(a[3]), "r"(b0), "r"(b1));
}
__device__ __forceinline__ void mma8(float* d, uint a0, uint a1, uint b0) {
    asm("mma.sync.aligned.m16n8k8.row.col.f32.bf16.bf16.f32 "
        "{%0,%1,%2,%3},{%4,%5},{%6},{%0,%1,%2,%3};"
        : "+f"(d[0]), "+f"(d[1]), "+f"(d[2]), "+f"(d[3])
        : "r"(a0), "r"(a1), "r"(b0));
}

// D fragments (8 x m16n8) -> lipswish -> bf16 -> A fragments of next layer.
__device__ __forceinline__ void epilogue(float d[8][4], uint Ahi[4][4]) {
#pragma unroll
    for (int nj = 0; nj < 8; nj++) {
        float a0 = lipswish(d[nj][0]);
        float a1 = lipswish(d[nj][1]);
        float a2 = lipswish(d[nj][2]);
        float a3 = lipswish(d[nj][3]);
        uint h01 = pack_bf16x2(a0, a1);
        uint h23 = pack_bf16x2(a2, a3);
        int kt = nj >> 1;
        if ((nj & 1) == 0) {
            Ahi[kt][0] = h01;
            Ahi[kt][1] = h23;
        } else {
            Ahi[kt][2] = h01;
            Ahi[kt][3] = h23;
        }
    }
}

// 64->64 hidden layer (M=16): A(bf16) x W(bf16 hi only) -> D -> epilogue -> A
__device__ __forceinline__ void hidden(const uint* __restrict__ usm, int wbase,
                                       const float* __restrict__ bias,
                                       uint Ahi[4][4], int lane, int tig) {
    float d[8][4];
#pragma unroll
    for (int nj = 0; nj < 8; nj++) {
        float2 b = *(const float2*)(bias + nj * 8 + 2 * tig);
        d[nj][0] = b.x; d[nj][1] = b.y; d[nj][2] = b.x; d[nj][3] = b.y;
    }
#pragma unroll
    for (int ktp = 0; ktp < 2; ktp++)
#pragma unroll
        for (int nj = 0; nj < 8; nj++) {
            int pos = ((ktp * 8 + nj) * 32 + lane) * 4;
            uint4 wh = *(const uint4*)(usm + wbase + pos);
            mma16(d[nj], Ahi[2 * ktp],     wh.x, wh.y);
            mma16(d[nj], Ahi[2 * ktp + 1], wh.z, wh.w);
        }
    epilogue(d, Ahi);
}

// Full MLP for one net (M=16): y(frag, split) -> d4[4] (one m16n8 D-frag, cols 0-3)
// L1 keeps 3-product y-split; L4 keeps weight hi+lo (final output precision).
__device__ __forceinline__ void net_eval(const uint* __restrict__ usm,
                                         const float* __restrict__ smf, int net,
                                         const uint yhi[2], const uint ylo[2],
                                         float* __restrict__ d4, int lane, int tig) {
    const float* bias = smf + OFF_B + net * 256;
    uint Ahi[4][4];
    // ---- L1: m16n8k8, K=4 padded to 8 ----
    {
        float d1[8][4];
#pragma unroll
        for (int nj = 0; nj < 8; nj++) {
            float2 b = *(const float2*)(bias + nj * 8 + 2 * tig);
            d1[nj][0] = b.x; d1[nj][1] = b.y; d1[nj][2] = b.x; d1[nj][3] = b.y;
        }
        int w1 = OFF_W1 + net * 512;
#pragma unroll
        for (int nj = 0; nj < 8; nj++) {
            uint wh = usm[w1 + nj * 32 + lane];
            uint wl = usm[w1 + 256 + nj * 32 + lane];
            mma8(d1[nj], yhi[0], yhi[1], wh);
            mma8(d1[nj], yhi[0], yhi[1], wl);
            mma8(d1[nj], ylo[0], ylo[1], wh);
        }
        epilogue(d1, Ahi);
    }
    hidden(usm, OFF_W2 + net * 2048, bias + 64,  Ahi, lane, tig);
    hidden(usm, OFF_W3 + net * 2048, bias + 128, Ahi, lane, tig);
    // ---- L4: m16n8k16, N=4 padded to 8, weight hi+lo ----
    {
        float2 bb = *(const float2*)(bias + 192 + 2 * tig);
        d4[0] = bb.x; d4[1] = bb.y; d4[2] = bb.x; d4[3] = bb.y;
        int w4 = OFF_W4 + net * 512;
#pragma unroll
        for (int ktp = 0; ktp < 2; ktp++) {
            int pos = (ktp * 32 + lane) * 4;
            uint4 wh = *(const uint4*)(usm + w4 + pos);
            uint4 wl = *(const uint4*)(usm + w4 + 256 + pos);
            mma16(d4, Ahi[2 * ktp],     wh.x, wh.y);
            mma16(d4, Ahi[2 * ktp],     wl.x, wl.y);
            mma16(d4, Ahi[2 * ktp + 1], wh.z, wh.w);
            mma16(d4, Ahi[2 * ktp + 1], wl.z, wl.w);
        }
    }
}

struct Params {
    const float* p[19];
    float* out;
};

__global__ __launch_bounds__(NTHR, 2) void sde_kernel(Params P) {
    extern __shared__ float smf[];
    uint* usm = (uint*)smf;
    const int tid = threadIdx.x;

    // ---------------- staging ----------------
    for (int i = tid; i < TSTEPS - 1; i += NTHR) {
        float dt = P.p[1][i + 1] - P.p[1][i];
        smf[OFF_DT + i] = dt;
        smf[OFF_SQ + i] = sqrtf(dt);
    }
    // biases (b4 padded to 8 with zeros)
    {
        const int bsrc[8] = {4, 6, 8, 10, 12, 14, 16, 18};
        for (int net = 0; net < 2; net++)
            for (int a = 0; a < 4; a++) {
                int cnt = (a < 3) ? 64 : 8;
                const float* src = P.p[bsrc[net * 4 + a]];
                for (int i = tid; i < cnt; i += NTHR)
                    smf[OFF_B + net * 256 + a * 64 + i] =
                        (a < 3 || i < 4) ? src[i] : 0.0f;
            }
    }
    // W2/W3 fragment-linear staging (bf16 hi only)
    {
        const float* Ws[4] = {P.p[5], P.p[13], P.p[7], P.p[15]};
        const int    bs[4] = {OFF_W2, OFF_W2 + 2048, OFF_W3, OFF_W3 + 2048};
        for (int nl = 0; nl < 4; nl++) {
            const float* S = Ws[nl];
            int base = bs[nl];
            for (int idx = tid; idx < 2048; idx += NTHR) {
                int w = idx & 3, lane = (idx >> 2) & 31;
                int nj = (idx >> 7) & 7, ktp = idx >> 10;
                int g = lane >> 2, tg = lane & 3;
                int kt = ktp * 2 + (w >> 1), breg = w & 1;
                int n = nj * 8 + g;
                int k0 = kt * 16 + 2 * tg + 8 * breg;
                usm[base + idx] = pack_bf16x2(S[k0 * 64 + n], S[(k0 + 1) * 64 + n]);
            }
        }
    }
    // W1 staging (K padded 4->8, hi+lo)
    {
        const float* W1s[2] = {P.p[3], P.p[11]};
        for (int net = 0; net < 2; net++)
            for (int idx = tid; idx < 256; idx += NTHR) {
                int lane = idx & 31, nj = idx >> 5;
                int g = lane >> 2, tg = lane & 3;
                int n = nj * 8 + g;
                int k0 = 2 * tg;
                float v0 = (k0 < 4)     ? W1s[net][k0 * 64 + n]       : 0.0f;
                float v1 = (k0 + 1 < 4) ? W1s[net][(k0 + 1) * 64 + n] : 0.0f;
                uint hi, lo;
                split2(v0, v1, hi, lo);
                usm[OFF_W1 + net * 512 + idx] = hi;
                usm[OFF_W1 + net * 512 + 256 + idx] = lo;
            }
    }
    // W4 staging (N padded 4->8, hi+lo)
    {
        const float* W4s[2] = {P.p[9], P.p[17]};
        for (int net = 0; net < 2; net++)
            for (int idx = tid; idx < 256; idx += NTHR) {
                int w = idx & 3, lane = (idx >> 2) & 31, ktp = idx >> 7;
                int g = lane >> 2, tg = lane & 3;
                int kt = ktp * 2 + (w >> 1), breg = w & 1;
                int n = g;
                int k0 = kt * 16 + 2 * tg + 8 * breg;
                float v0 = (n < 4) ? W4s[net][k0 * 4 + n]       : 0.0f;
                float v1 = (n < 4) ? W4s[net][(k0 + 1) * 4 + n] : 0.0f;
                uint hi, lo;
                split2(v0, v1, hi, lo);
                usm[OFF_W4 + net * 512 + idx] = hi;
                usm[OFF_W4 + net * 512 + 256 + idx] = lo;
            }
    }
    __syncthreads();

    // ---------------- per-warp fragment-domain SDE loop (16 samples/warp) ----------------
    const int lane = tid & 31;
    const int g = lane >> 2, tig = lane & 3;
    const int gw = blockIdx.x * (NTHR / 32) + (tid >> 5);
    const int sbase = gw * 16;
    if (sbase >= NSMP) return;          // tail warps (3 of 2051) exit whole
    const bool ldok = (tig < 2);

    const float* y0 = P.p[0];
    const float* nz = P.p[2];
    float* out = P.out;

    // y in D-fragment form: y[0..3] = rows (sbase+g, +8) x cols (2tig, 2tig+1)
    float y[4];
    const int r0 = sbase + g;
    if (ldok) {
        float2 v0 = *(const float2*)(y0 + r0 * 4 + 2 * tig);
        float2 v1 = *(const float2*)(y0 + (r0 + 8) * 4 + 2 * tig);
        y[0] = v0.x; y[1] = v0.y; y[2] = v1.x; y[3] = v1.y;
        *(float2*)(out + (size_t)r0 * TSTEPS * 4 + 2 * tig) = v0;
        *(float2*)(out + (size_t)(r0 + 8) * TSTEPS * 4 + 2 * tig) = v1;
    } else {
        y[0] = y[1] = y[2] = y[3] = 0.0f;
    }
    uint yhi[2], ylo[2];
    split2(y[0], y[1], yhi[0], ylo[0]);
    split2(y[2], y[3], yhi[1], ylo[1]);

    for (int t = 0; t < TSTEPS - 1; t++) {
        float dwv[4];
        if (ldok) {
            const float* b = nz + ((size_t)t * NSMP) * 4;
            float2 v0 = *(const float2*)(b + r0 * 4 + 2 * tig);
            float2 v1 = *(const float2*)(b + (r0 + 8) * 4 + 2 * tig);
            dwv[0] = v0.x; dwv[1] = v0.y; dwv[2] = v1.x; dwv[3] = v1.y;
        } else {
            dwv[0] = dwv[1] = dwv[2] = dwv[3] = 0.0f;
        }

        float df[4], dg[4];
        net_eval(usm, smf, 0, yhi, ylo, df, lane, tig);
        net_eval(usm, smf, 1, yhi, ylo, dg, lane, tig);

        float dt = smf[OFF_DT + t];
        float sq = smf[OFF_SQ + t];

#pragma unroll
        for (int j = 0; j < 4; j++) {
            float f = fminf(fmaxf(df[j], -100.0f), 100.0f);
            float gg = fmaxf(softplus_acc(dg[j]), 1e-4f);
            y[j] = y[j] + f * dt + gg * sq * dwv[j];
        }

        if (ldok) {
            *(float2*)(out + ((size_t)r0 * TSTEPS + t + 1) * 4 + 2 * tig) =
                make_float2(y[0], y[1]);
            *(float2*)(out + ((size_t)(r0 + 8) * TSTEPS + t + 1) * 4 + 2 * tig) =
                make_float2(y[2], y[3]);
        }
        split2(y[0], y[1], yhi[0], ylo[0]);
        split2(y[2], y[3], yhi[1], ylo[1]);
    }
}

extern "C" void kernel_launch(void* const* d_in, const int* in_sizes, int n_in,
                              void* d_out, int out_size) {
    Params P;
    for (int i = 0; i < 19; i++) P.p[i] = (const float*)d_in[i];
    P.out = (float*)d_out;

    cudaFuncSetAttribute(sde_kernel, cudaFuncAttributeMaxDynamicSharedMemorySize,
                         SMEM_BYTES);
    sde_kernel<<<NCTA, NTHR, SMEM_BYTES>>>(P);
}